// round 2
// baseline (speedup 1.0000x reference)
#include <cuda_runtime.h>
#include <cstdint>

typedef unsigned long long ull;

// ---------------- device scratch (static, no runtime alloc) ----------------
__device__ float g_s1[2048 * 32 * 14 * 14];   // stage1 out: [B,32,14,14]
__device__ float g_s2[2048 * 3136];           // stage2 out: [B,64*7*7]
__device__ float g_fc1[2048 * 1024];          // fc1 out
__device__ float g_w2t[32 * 25 * 64];         // conv2 w transposed: [ci][tap][co]

// ---------------- f32x2 helpers (FFMA2 full-rate fp32 path) ----------------
__device__ __forceinline__ ull ffma2(ull a, ull b, ull c) {
    ull d;
    asm("fma.rn.f32x2 %0, %1, %2, %3;" : "=l"(d) : "l"(a), "l"(b), "l"(c));
    return d;
}
__device__ __forceinline__ ull dup2(float v) {
    ull d; asm("mov.b64 %0, {%1, %1};" : "=l"(d) : "f"(v)); return d;
}
__device__ __forceinline__ ull pk2(float lo, float hi) {
    ull d; asm("mov.b64 %0, {%1, %2};" : "=l"(d) : "f"(lo), "f"(hi)); return d;
}
__device__ __forceinline__ void upk2(ull v, float& lo, float& hi) {
    asm("mov.b64 {%0, %1}, %2;" : "=f"(lo), "=f"(hi) : "l"(v));
}

// ---------------- cp.async helpers ----------------
__device__ __forceinline__ void cp16(float* s, const float* g) {
    unsigned sa = (unsigned)__cvta_generic_to_shared(s);
    asm volatile("cp.async.ca.shared.global [%0], [%1], 16;" :: "r"(sa), "l"(g));
}
__device__ __forceinline__ void cp_commit() { asm volatile("cp.async.commit_group;"); }
__device__ __forceinline__ void cp_wait0()  { asm volatile("cp.async.wait_group 0;"); }

// ---------------- top-4 insertion (a>=b>=c>=d) ----------------
__device__ __forceinline__ void ins4(float& a, float& b, float& c, float& d, float v) {
    if (v > d) {
        d = v;
        if (d > c) { float t = c; c = d; d = t;
            if (c > b) { t = b; b = c; c = t;
                if (b > a) { t = a; a = b; b = t; }
            }
        }
    }
}

// ============================================================================
// prep: transpose conv2_w [co][ci][tap] -> [ci][tap][co]
// ============================================================================
__global__ void k_prep(const float* __restrict__ w2) {
    int i = blockIdx.x * blockDim.x + threadIdx.x;
    if (i < 64 * 32 * 25) {
        int co = i / 800, r = i % 800, ci = r / 25, tap = r % 25;
        g_w2t[(ci * 25 + tap) * 64 + co] = w2[i];
    }
}

// ============================================================================
// conv1 (1->32, 5x5, pad2) + top-4 channel mask + threshold ReLU + 2x2 maxpool
// block = 2 images, 392 threads; thread = one 2x2 output quad.
// f32x2 lanes = (top pixel, bottom pixel); two accumulators = two columns.
// ============================================================================
__global__ void __launch_bounds__(392) k_conv1(const float* __restrict__ xin,
                                               const float* __restrict__ w1,
                                               const float* __restrict__ tt) {
    __shared__ float s_in[2][1024];     // padded 32x32 per image
    __shared__ ull   s_w[800];          // dup-packed weights (w,w)
    __shared__ float s_t[32];

    int tid = threadIdx.x;
    int img0 = blockIdx.x * 2;

    for (int i = tid; i < 800; i += 392) { float v = w1[i]; s_w[i] = dup2(v); }
    if (tid < 32) s_t[tid] = tt[tid];
    for (int i = tid; i < 2048; i += 392) ((float*)s_in)[i] = 0.f;
    __syncthreads();
    for (int i = tid; i < 1568; i += 392) {
        int im = i / 784, p = i % 784, y = p / 28, xx = p % 28;
        s_in[im][(y + 2) * 32 + xx + 2] = xin[(img0 + im) * 784 + p];
    }
    __syncthreads();

    int im = tid / 196, t = tid % 196;
    int py = t / 14, px = t % 14;
    const float* base = &s_in[im][(2 * py) * 32 + 2 * px];

    // window 6x6, packed vertical pairs pr[dy][c] = (row dy, row dy+1), dy 0..4, c 0..5
    float win[6][6];
#pragma unroll
    for (int r = 0; r < 6; r++)
#pragma unroll
        for (int c = 0; c < 6; c++) win[r][c] = base[r * 32 + c];
    ull pr[30];
#pragma unroll
    for (int dy = 0; dy < 5; dy++)
#pragma unroll
        for (int c = 0; c < 6; c++) pr[dy * 6 + c] = pk2(win[dy][c], win[dy + 1][c]);

    // pass A: top-4 per pixel
    float a0t = -3.4e38f, b0t = -3.4e38f, c0t = -3.4e38f, d0t = -3.4e38f;
    float a1t = -3.4e38f, b1t = -3.4e38f, c1t = -3.4e38f, d1t = -3.4e38f;
    float a2t = -3.4e38f, b2t = -3.4e38f, c2t = -3.4e38f, d2t = -3.4e38f;
    float a3t = -3.4e38f, b3t = -3.4e38f, c3t = -3.4e38f, d3t = -3.4e38f;

    for (int c = 0; c < 32; c++) {
        const ull* wc = &s_w[c * 25];
        ull A0 = 0ull, A1 = 0ull;
#pragma unroll
        for (int dy = 0; dy < 5; dy++)
#pragma unroll
            for (int dx = 0; dx < 5; dx++) {
                ull wv = wc[dy * 5 + dx];
                A0 = ffma2(pr[dy * 6 + dx], wv, A0);
                A1 = ffma2(pr[dy * 6 + dx + 1], wv, A1);
            }
        float v00, v10, v01, v11;
        upk2(A0, v00, v10); upk2(A1, v01, v11);
        ins4(a0t, b0t, c0t, d0t, v00);
        ins4(a1t, b1t, c1t, d1t, v10);
        ins4(a2t, b2t, c2t, d2t, v01);
        ins4(a3t, b3t, c3t, d3t, v11);
    }
    float k0 = d0t, k1 = d1t, k2 = d2t, k3 = d3t;

    // pass B: recompute, mask by kth, threshold-relu, 2x2 max, store
    int img = img0 + im;
    for (int c = 0; c < 32; c++) {
        const ull* wc = &s_w[c * 25];
        ull A0 = 0ull, A1 = 0ull;
#pragma unroll
        for (int dy = 0; dy < 5; dy++)
#pragma unroll
            for (int dx = 0; dx < 5; dx++) {
                ull wv = wc[dy * 5 + dx];
                A0 = ffma2(pr[dy * 6 + dx], wv, A0);
                A1 = ffma2(pr[dy * 6 + dx + 1], wv, A1);
            }
        float v00, v10, v01, v11;
        upk2(A0, v00, v10); upk2(A1, v01, v11);
        float tc = s_t[c];
        float r0 = (v00 >= k0) ? fmaxf(v00 - tc, 0.f) : 0.f;
        float r1 = (v10 >= k1) ? fmaxf(v10 - tc, 0.f) : 0.f;
        float r2 = (v01 >= k2) ? fmaxf(v01 - tc, 0.f) : 0.f;
        float r3 = (v11 >= k3) ? fmaxf(v11 - tc, 0.f) : 0.f;
        float m = fmaxf(fmaxf(r0, r1), fmaxf(r2, r3));
        g_s1[((img * 32 + c) * 14 + py) * 14 + px] = m;
    }
}

// ============================================================================
// conv2 (32->64, 5x5, pad2, 14x14) + bias + relu + 2x2 maxpool
// block = 2 images, 392 threads: thread = (image, co-half of 32, vertical
// pixel pair). f32x2 lanes = adjacent output channels. Weights staged per-ci
// via cp.async double buffer; broadcast LDS.128 reads.
// ============================================================================
__global__ void __launch_bounds__(392) k_conv2(const float* __restrict__ b2) {
    extern __shared__ float sm[];
    float* s_in = sm;              // 2 * 32*18*18 = 20736 floats (padded inputs)
    float* s_w  = sm + 20736;      // 2 * 1600 floats (double-buffered w slice)

    int tid = threadIdx.x;
    int img0 = blockIdx.x * 2;

    for (int i = tid; i < 20736; i += 392) s_in[i] = 0.f;
    __syncthreads();
    for (int i = tid; i < 12544; i += 392) {
        int im = i / 6272, r = i % 6272, ci = r / 196, p = r % 196;
        int y = p / 14, xx = p % 14;
        s_in[im * 10368 + ci * 324 + (y + 2) * 18 + xx + 2] =
            g_s1[(((img0 + im) * 32 + ci) * 14 + y) * 14 + xx];
    }
    // prefetch weights for ci=0
    for (int i = tid; i < 400; i += 392) cp16(&s_w[i * 4], g_w2t + i * 4);
    cp_commit();

    int im = tid / 196, t = tid % 196, h = t / 98, q = t % 98;
    int qy = q / 14, xx = q % 14;
    const float* inb = s_in + im * 10368;
    int rowbase = (2 * qy) * 18 + xx;
    int coB = h * 32;

    ull acc0[16], acc1[16];
#pragma unroll
    for (int j = 0; j < 16; j++) { acc0[j] = 0ull; acc1[j] = 0ull; }

    for (int ci = 0; ci < 32; ci++) {
        cp_wait0();
        __syncthreads();
        int buf = ci & 1;
        if (ci < 31) {
            const float* src = g_w2t + (ci + 1) * 1600;
            float* dst = s_w + (1 - buf) * 1600;
            for (int i = tid; i < 400; i += 392) cp16(dst + i * 4, src + i * 4);
            cp_commit();
        }
        const float* ip = inb + ci * 324 + rowbase;
        const float* wp = s_w + buf * 1600 + coB;

        ull rA[5], rB[5];
#pragma unroll
        for (int c = 0; c < 5; c++) rA[c] = dup2(ip[c]);
#pragma unroll
        for (int dy = 0; dy < 5; dy++) {
            const float* rp = ip + (dy + 1) * 18;
#pragma unroll
            for (int c = 0; c < 5; c++) rB[c] = dup2(rp[c]);
#pragma unroll
            for (int dx = 0; dx < 5; dx++) {
                const ulonglong2* wv =
                    reinterpret_cast<const ulonglong2*>(wp + (dy * 5 + dx) * 64);
                ull ra = rA[dx], rb = rB[dx];
#pragma unroll
                for (int jj = 0; jj < 8; jj++) {
                    ulonglong2 ww = wv[jj];
                    acc0[2 * jj]     = ffma2(ra, ww.x, acc0[2 * jj]);
                    acc0[2 * jj + 1] = ffma2(ra, ww.y, acc0[2 * jj + 1]);
                    acc1[2 * jj]     = ffma2(rb, ww.x, acc1[2 * jj]);
                    acc1[2 * jj + 1] = ffma2(rb, ww.y, acc1[2 * jj + 1]);
                }
            }
#pragma unroll
            for (int c = 0; c < 5; c++) rA[c] = rB[c];
        }
    }

    // epilogue: bias + relu + vertical max -> smem -> horizontal max -> store
    __syncthreads();
    float* sx = sm;  // reuse input region (padded stride 33 vs bank conflicts)
#pragma unroll
    for (int jj = 0; jj < 16; jj++) {
        float a, b, c, d;
        upk2(acc0[jj], a, b);
        upk2(acc1[jj], c, d);
        int co = coB + 2 * jj;
        float b0 = b2[co], b1 = b2[co + 1];
        float m0 = fmaxf(fmaxf(a + b0, 0.f), fmaxf(c + b0, 0.f));
        float m1 = fmaxf(fmaxf(b + b1, 0.f), fmaxf(d + b1, 0.f));
        sx[tid * 33 + 2 * jj] = m0;
        sx[tid * 33 + 2 * jj + 1] = m1;
    }
    __syncthreads();
    if (!(xx & 1)) {
        int img = img0 + im;
        int qx = xx >> 1;
#pragma unroll
        for (int c = 0; c < 32; c++) {
            float v = fmaxf(sx[tid * 33 + c], sx[(tid + 1) * 33 + c]);
            g_s2[img * 3136 + (coB + c) * 49 + qy * 7 + qx] = v;
        }
    }
}

// ============================================================================
// fc1: [2048,3136] x [1024,3136]^T + b, relu. Tiled GEMM BM=128 BN=64 BK=16,
// 256 threads, 8x4 microtile, f32x2 accumulation, double-buffered smem.
// ============================================================================
__global__ void __launch_bounds__(256) k_fc1(const float* __restrict__ w,
                                             const float* __restrict__ b) {
    __shared__ __align__(16) float As[2][16][132];
    __shared__ __align__(16) float Bs[2][16][68];

    int tid = threadIdx.x;
    int bm0 = blockIdx.x * 128, bn0 = blockIdx.y * 64;
    int tm = tid >> 4, tn = tid & 15;
    int m0 = tm * 8, n0 = tn * 4;
    int arow = tid >> 2, akq = tid & 3;

    ull acc[8][2];
#pragma unroll
    for (int i = 0; i < 8; i++) { acc[i][0] = 0ull; acc[i][1] = 0ull; }

    float4 aR0, aR1, bR;
    {
        int k0 = 0;
        aR0 = *reinterpret_cast<const float4*>(&g_s2[(bm0 + arow) * 3136 + k0 + akq * 4]);
        aR1 = *reinterpret_cast<const float4*>(&g_s2[(bm0 + arow + 64) * 3136 + k0 + akq * 4]);
        bR  = *reinterpret_cast<const float4*>(&w[(bn0 + arow) * 3136 + k0 + akq * 4]);
    }
    {
        int kb = akq * 4;
        As[0][kb + 0][arow] = aR0.x; As[0][kb + 1][arow] = aR0.y;
        As[0][kb + 2][arow] = aR0.z; As[0][kb + 3][arow] = aR0.w;
        As[0][kb + 0][arow + 64] = aR1.x; As[0][kb + 1][arow + 64] = aR1.y;
        As[0][kb + 2][arow + 64] = aR1.z; As[0][kb + 3][arow + 64] = aR1.w;
        Bs[0][kb + 0][arow] = bR.x; Bs[0][kb + 1][arow] = bR.y;
        Bs[0][kb + 2][arow] = bR.z; Bs[0][kb + 3][arow] = bR.w;
    }
    __syncthreads();

    for (int kt = 0; kt < 196; kt++) {
        int s = kt & 1;
        if (kt < 195) {
            int k0 = (kt + 1) * 16;
            aR0 = *reinterpret_cast<const float4*>(&g_s2[(bm0 + arow) * 3136 + k0 + akq * 4]);
            aR1 = *reinterpret_cast<const float4*>(&g_s2[(bm0 + arow + 64) * 3136 + k0 + akq * 4]);
            bR  = *reinterpret_cast<const float4*>(&w[(bn0 + arow) * 3136 + k0 + akq * 4]);
        }
#pragma unroll
        for (int k = 0; k < 16; k++) {
            float4 a0 = *reinterpret_cast<const float4*>(&As[s][k][m0]);
            float4 a1 = *reinterpret_cast<const float4*>(&As[s][k][m0 + 4]);
            float4 b4 = *reinterpret_cast<const float4*>(&Bs[s][k][n0]);
            ull pb0 = pk2(b4.x, b4.y), pb1 = pk2(b4.z, b4.w);
            ull pa;
            pa = dup2(a0.x); acc[0][0] = ffma2(pa, pb0, acc[0][0]); acc[0][1] = ffma2(pa, pb1, acc[0][1]);
            pa = dup2(a0.y); acc[1][0] = ffma2(pa, pb0, acc[1][0]); acc[1][1] = ffma2(pa, pb1, acc[1][1]);
            pa = dup2(a0.z); acc[2][0] = ffma2(pa, pb0, acc[2][0]); acc[2][1] = ffma2(pa, pb1, acc[2][1]);
            pa = dup2(a0.w); acc[3][0] = ffma2(pa, pb0, acc[3][0]); acc[3][1] = ffma2(pa, pb1, acc[3][1]);
            pa = dup2(a1.x); acc[4][0] = ffma2(pa, pb0, acc[4][0]); acc[4][1] = ffma2(pa, pb1, acc[4][1]);
            pa = dup2(a1.y); acc[5][0] = ffma2(pa, pb0, acc[5][0]); acc[5][1] = ffma2(pa, pb1, acc[5][1]);
            pa = dup2(a1.z); acc[6][0] = ffma2(pa, pb0, acc[6][0]); acc[6][1] = ffma2(pa, pb1, acc[6][1]);
            pa = dup2(a1.w); acc[7][0] = ffma2(pa, pb0, acc[7][0]); acc[7][1] = ffma2(pa, pb1, acc[7][1]);
        }
        if (kt < 195) {
            int ns = 1 - s;
            int kb = akq * 4;
            As[ns][kb + 0][arow] = aR0.x; As[ns][kb + 1][arow] = aR0.y;
            As[ns][kb + 2][arow] = aR0.z; As[ns][kb + 3][arow] = aR0.w;
            As[ns][kb + 0][arow + 64] = aR1.x; As[ns][kb + 1][arow + 64] = aR1.y;
            As[ns][kb + 2][arow + 64] = aR1.z; As[ns][kb + 3][arow + 64] = aR1.w;
            Bs[ns][kb + 0][arow] = bR.x; Bs[ns][kb + 1][arow] = bR.y;
            Bs[ns][kb + 2][arow] = bR.z; Bs[ns][kb + 3][arow] = bR.w;
            __syncthreads();
        }
    }

#pragma unroll
    for (int i = 0; i < 8; i++) {
        int m = bm0 + m0 + i, gn = bn0 + n0;
        float r0, r1, r2, r3;
        upk2(acc[i][0], r0, r1);
        upk2(acc[i][1], r2, r3);
        float4 o;
        o.x = fmaxf(r0 + b[gn + 0], 0.f);
        o.y = fmaxf(r1 + b[gn + 1], 0.f);
        o.z = fmaxf(r2 + b[gn + 2], 0.f);
        o.w = fmaxf(r3 + b[gn + 3], 0.f);
        *reinterpret_cast<float4*>(&g_fc1[m * 1024 + gn]) = o;
    }
}

// ============================================================================
// fc2: [2048,1024] x [10,1024]^T + b. Warp per row.
// ============================================================================
__global__ void __launch_bounds__(256) k_fc2(const float* __restrict__ w,
                                             const float* __restrict__ b,
                                             float* __restrict__ out) {
    int warp = threadIdx.x >> 5, lane = threadIdx.x & 31;
    int row = blockIdx.x * 8 + warp;
    const float* a = &g_fc1[row * 1024];
    float acc[10];
#pragma unroll
    for (int n = 0; n < 10; n++) acc[n] = 0.f;
    for (int k = lane; k < 1024; k += 32) {
        float av = a[k];
#pragma unroll
        for (int n = 0; n < 10; n++) acc[n] += av * w[n * 1024 + k];
    }
#pragma unroll
    for (int n = 0; n < 10; n++)
#pragma unroll
        for (int off = 16; off > 0; off >>= 1)
            acc[n] += __shfl_xor_sync(0xffffffffu, acc[n], off);
    if (lane == 0) {
#pragma unroll
        for (int n = 0; n < 10; n++) out[row * 10 + n] = acc[n] + b[n];
    }
}

// ============================================================================
extern "C" void kernel_launch(void* const* d_in, const int* in_sizes, int n_in,
                              void* d_out, int out_size) {
    const float* x       = (const float*)d_in[0];
    const float* conv1_w = (const float*)d_in[1];
    const float* trelu_t = (const float*)d_in[2];
    const float* conv2_w = (const float*)d_in[3];
    const float* conv2_b = (const float*)d_in[4];
    const float* fc1_w   = (const float*)d_in[5];
    const float* fc1_b   = (const float*)d_in[6];
    const float* fc2_w   = (const float*)d_in[7];
    const float* fc2_b   = (const float*)d_in[8];
    float* out = (float*)d_out;

    const int SMEM2 = (2 * 10368 + 2 * 1600) * 4;  // 95744 B
    cudaFuncSetAttribute(k_conv2, cudaFuncAttributeMaxDynamicSharedMemorySize, SMEM2);

    k_prep<<<(64 * 32 * 25 + 255) / 256, 256>>>(conv2_w);
    k_conv1<<<1024, 392>>>(x, conv1_w, trelu_t);
    k_conv2<<<1024, 392, SMEM2>>>(conv2_b);
    k_fc1<<<dim3(16, 16), 256>>>(fc1_w, fc1_b);
    k_fc2<<<256, 256>>>(fc2_w, fc2_b, out);
}

// round 3
// speedup vs baseline: 1.0016x; 1.0016x over previous
#include <cuda_runtime.h>
#include <cstdint>

typedef unsigned long long ull;

// ---------------- device scratch (static, no runtime alloc) ----------------
__device__ float g_s1[2048 * 32 * 14 * 14];   // stage1 out: [B,32,14,14]
__device__ float g_s2[2048 * 3136];           // stage2 out: [B,64*7*7]
__device__ float g_fc1[2048 * 1024];          // fc1 out
__device__ float g_w2t[32 * 25 * 64];         // conv2 w transposed: [ci][tap][co]

// ---------------- f32x2 helpers (FFMA2 full-rate fp32 path) ----------------
__device__ __forceinline__ ull ffma2(ull a, ull b, ull c) {
    ull d;
    asm("fma.rn.f32x2 %0, %1, %2, %3;" : "=l"(d) : "l"(a), "l"(b), "l"(c));
    return d;
}
__device__ __forceinline__ ull dup2(float v) {
    ull d; asm("mov.b64 %0, {%1, %1};" : "=l"(d) : "f"(v)); return d;
}
__device__ __forceinline__ ull pk2(float lo, float hi) {
    ull d; asm("mov.b64 %0, {%1, %2};" : "=l"(d) : "f"(lo), "f"(hi)); return d;
}
__device__ __forceinline__ void upk2(ull v, float& lo, float& hi) {
    asm("mov.b64 {%0, %1}, %2;" : "=f"(lo), "=f"(hi) : "l"(v));
}

// ---------------- cp.async helpers ----------------
__device__ __forceinline__ void cp16(float* s, const float* g) {
    unsigned sa = (unsigned)__cvta_generic_to_shared(s);
    asm volatile("cp.async.ca.shared.global [%0], [%1], 16;" :: "r"(sa), "l"(g));
}
__device__ __forceinline__ void cp_commit() { asm volatile("cp.async.commit_group;"); }
__device__ __forceinline__ void cp_wait0()  { asm volatile("cp.async.wait_group 0;"); }

// ---------------- top-4 insertion (a>=b>=c>=d) ----------------
__device__ __forceinline__ void ins4(float& a, float& b, float& c, float& d, float v) {
    if (v > d) {
        d = v;
        if (d > c) { float t = c; c = d; d = t;
            if (c > b) { t = b; b = c; c = t;
                if (b > a) { t = a; a = b; b = t; }
            }
        }
    }
}

// ============================================================================
// prep: transpose conv2_w [co][ci][tap] -> [ci][tap][co]
// ============================================================================
__global__ void k_prep(const float* __restrict__ w2) {
    int i = blockIdx.x * blockDim.x + threadIdx.x;
    if (i < 64 * 32 * 25) {
        int co = i / 800, r = i % 800, ci = r / 25, tap = r % 25;
        g_w2t[(ci * 25 + tap) * 64 + co] = w2[i];
    }
}

// ============================================================================
// conv1 (1->32, 5x5, pad2) + top-4 channel mask + threshold ReLU + 2x2 maxpool
// block = 2 images, 392 threads; thread = one 2x2 output quad.
// f32x2 lanes = (top pixel, bottom pixel); two accumulators = two columns.
// ============================================================================
__global__ void __launch_bounds__(392) k_conv1(const float* __restrict__ xin,
                                               const float* __restrict__ w1,
                                               const float* __restrict__ tt) {
    __shared__ float s_in[2][1024];     // padded 32x32 per image
    __shared__ ull   s_w[800];          // dup-packed weights (w,w)
    __shared__ float s_t[32];

    int tid = threadIdx.x;
    int img0 = blockIdx.x * 2;

    for (int i = tid; i < 800; i += 392) { float v = w1[i]; s_w[i] = dup2(v); }
    if (tid < 32) s_t[tid] = tt[tid];
    for (int i = tid; i < 2048; i += 392) ((float*)s_in)[i] = 0.f;
    __syncthreads();
    for (int i = tid; i < 1568; i += 392) {
        int im = i / 784, p = i % 784, y = p / 28, xx = p % 28;
        s_in[im][(y + 2) * 32 + xx + 2] = xin[(img0 + im) * 784 + p];
    }
    __syncthreads();

    int im = tid / 196, t = tid % 196;
    int py = t / 14, px = t % 14;
    const float* base = &s_in[im][(2 * py) * 32 + 2 * px];

    // window 6x6, packed vertical pairs pr[dy][c] = (row dy, row dy+1), dy 0..4, c 0..5
    float win[6][6];
#pragma unroll
    for (int r = 0; r < 6; r++)
#pragma unroll
        for (int c = 0; c < 6; c++) win[r][c] = base[r * 32 + c];
    ull pr[30];
#pragma unroll
    for (int dy = 0; dy < 5; dy++)
#pragma unroll
        for (int c = 0; c < 6; c++) pr[dy * 6 + c] = pk2(win[dy][c], win[dy + 1][c]);

    // pass A: top-4 per pixel
    float a0t = -3.4e38f, b0t = -3.4e38f, c0t = -3.4e38f, d0t = -3.4e38f;
    float a1t = -3.4e38f, b1t = -3.4e38f, c1t = -3.4e38f, d1t = -3.4e38f;
    float a2t = -3.4e38f, b2t = -3.4e38f, c2t = -3.4e38f, d2t = -3.4e38f;
    float a3t = -3.4e38f, b3t = -3.4e38f, c3t = -3.4e38f, d3t = -3.4e38f;

    for (int c = 0; c < 32; c++) {
        const ull* wc = &s_w[c * 25];
        ull A0 = 0ull, A1 = 0ull;
#pragma unroll
        for (int dy = 0; dy < 5; dy++)
#pragma unroll
            for (int dx = 0; dx < 5; dx++) {
                ull wv = wc[dy * 5 + dx];
                A0 = ffma2(pr[dy * 6 + dx], wv, A0);
                A1 = ffma2(pr[dy * 6 + dx + 1], wv, A1);
            }
        float v00, v10, v01, v11;
        upk2(A0, v00, v10); upk2(A1, v01, v11);
        ins4(a0t, b0t, c0t, d0t, v00);
        ins4(a1t, b1t, c1t, d1t, v10);
        ins4(a2t, b2t, c2t, d2t, v01);
        ins4(a3t, b3t, c3t, d3t, v11);
    }
    float k0 = d0t, k1 = d1t, k2 = d2t, k3 = d3t;

    // pass B: recompute, mask by kth, threshold-relu, 2x2 max, store
    int img = img0 + im;
    for (int c = 0; c < 32; c++) {
        const ull* wc = &s_w[c * 25];
        ull A0 = 0ull, A1 = 0ull;
#pragma unroll
        for (int dy = 0; dy < 5; dy++)
#pragma unroll
            for (int dx = 0; dx < 5; dx++) {
                ull wv = wc[dy * 5 + dx];
                A0 = ffma2(pr[dy * 6 + dx], wv, A0);
                A1 = ffma2(pr[dy * 6 + dx + 1], wv, A1);
            }
        float v00, v10, v01, v11;
        upk2(A0, v00, v10); upk2(A1, v01, v11);
        float tc = s_t[c];
        float r0 = (v00 >= k0) ? fmaxf(v00 - tc, 0.f) : 0.f;
        float r1 = (v10 >= k1) ? fmaxf(v10 - tc, 0.f) : 0.f;
        float r2 = (v01 >= k2) ? fmaxf(v01 - tc, 0.f) : 0.f;
        float r3 = (v11 >= k3) ? fmaxf(v11 - tc, 0.f) : 0.f;
        float m = fmaxf(fmaxf(r0, r1), fmaxf(r2, r3));
        g_s1[((img * 32 + c) * 14 + py) * 14 + px] = m;
    }
}

// ============================================================================
// conv2 (32->64, 5x5, pad2, 14x14) + bias + relu + 2x2 maxpool
// block = 2 images, 392 threads: thread = (image, co-half of 32, vertical
// pixel pair). f32x2 lanes = adjacent output channels. Weights staged per-ci
// via cp.async double buffer; broadcast LDS.128 reads.
// ============================================================================
__global__ void __launch_bounds__(392) k_conv2(const float* __restrict__ b2) {
    extern __shared__ float sm[];
    float* s_in = sm;              // 2 * 32*18*18 = 20736 floats (padded inputs)
    float* s_w  = sm + 20736;      // 2 * 1600 floats (double-buffered w slice)

    int tid = threadIdx.x;
    int img0 = blockIdx.x * 2;

    for (int i = tid; i < 20736; i += 392) s_in[i] = 0.f;
    __syncthreads();
    for (int i = tid; i < 12544; i += 392) {
        int im = i / 6272, r = i % 6272, ci = r / 196, p = r % 196;
        int y = p / 14, xx = p % 14;
        s_in[im * 10368 + ci * 324 + (y + 2) * 18 + xx + 2] =
            g_s1[(((img0 + im) * 32 + ci) * 14 + y) * 14 + xx];
    }
    // prefetch weights for ci=0
    for (int i = tid; i < 400; i += 392) cp16(&s_w[i * 4], g_w2t + i * 4);
    cp_commit();

    int im = tid / 196, t = tid % 196, h = t / 98, q = t % 98;
    int qy = q / 14, xx = q % 14;
    const float* inb = s_in + im * 10368;
    int rowbase = (2 * qy) * 18 + xx;
    int coB = h * 32;

    ull acc0[16], acc1[16];
#pragma unroll
    for (int j = 0; j < 16; j++) { acc0[j] = 0ull; acc1[j] = 0ull; }

    for (int ci = 0; ci < 32; ci++) {
        cp_wait0();
        __syncthreads();
        int buf = ci & 1;
        if (ci < 31) {
            const float* src = g_w2t + (ci + 1) * 1600;
            float* dst = s_w + (1 - buf) * 1600;
            for (int i = tid; i < 400; i += 392) cp16(dst + i * 4, src + i * 4);
            cp_commit();
        }
        const float* ip = inb + ci * 324 + rowbase;
        const float* wp = s_w + buf * 1600 + coB;

        ull rA[5], rB[5];
#pragma unroll
        for (int c = 0; c < 5; c++) rA[c] = dup2(ip[c]);
#pragma unroll
        for (int dy = 0; dy < 5; dy++) {
            const float* rp = ip + (dy + 1) * 18;
#pragma unroll
            for (int c = 0; c < 5; c++) rB[c] = dup2(rp[c]);
#pragma unroll
            for (int dx = 0; dx < 5; dx++) {
                const ulonglong2* wv =
                    reinterpret_cast<const ulonglong2*>(wp + (dy * 5 + dx) * 64);
                ull ra = rA[dx], rb = rB[dx];
#pragma unroll
                for (int jj = 0; jj < 8; jj++) {
                    ulonglong2 ww = wv[jj];
                    acc0[2 * jj]     = ffma2(ra, ww.x, acc0[2 * jj]);
                    acc0[2 * jj + 1] = ffma2(ra, ww.y, acc0[2 * jj + 1]);
                    acc1[2 * jj]     = ffma2(rb, ww.x, acc1[2 * jj]);
                    acc1[2 * jj + 1] = ffma2(rb, ww.y, acc1[2 * jj + 1]);
                }
            }
#pragma unroll
            for (int c = 0; c < 5; c++) rA[c] = rB[c];
        }
    }

    // epilogue: bias + relu + vertical max -> smem -> horizontal max -> store
    __syncthreads();
    float* sx = sm;  // reuse input region (padded stride 33 vs bank conflicts)
#pragma unroll
    for (int jj = 0; jj < 16; jj++) {
        float a, b, c, d;
        upk2(acc0[jj], a, b);
        upk2(acc1[jj], c, d);
        int co = coB + 2 * jj;
        float b0 = b2[co], b1 = b2[co + 1];
        float m0 = fmaxf(fmaxf(a + b0, 0.f), fmaxf(c + b0, 0.f));
        float m1 = fmaxf(fmaxf(b + b1, 0.f), fmaxf(d + b1, 0.f));
        sx[tid * 33 + 2 * jj] = m0;
        sx[tid * 33 + 2 * jj + 1] = m1;
    }
    __syncthreads();
    if (!(xx & 1)) {
        int img = img0 + im;
        int qx = xx >> 1;
#pragma unroll
        for (int c = 0; c < 32; c++) {
            float v = fmaxf(sx[tid * 33 + c], sx[(tid + 1) * 33 + c]);
            g_s2[img * 3136 + (coB + c) * 49 + qy * 7 + qx] = v;
        }
    }
}

// ============================================================================
// fc1: [2048,3136] x [1024,3136]^T + b, relu. Tiled GEMM BM=128 BN=64 BK=16,
// 256 threads, 8x4 microtile, f32x2 accumulation, double-buffered smem.
// ============================================================================
__global__ void __launch_bounds__(256) k_fc1(const float* __restrict__ w,
                                             const float* __restrict__ b) {
    __shared__ __align__(16) float As[2][16][132];
    __shared__ __align__(16) float Bs[2][16][68];

    int tid = threadIdx.x;
    int bm0 = blockIdx.x * 128, bn0 = blockIdx.y * 64;
    int tm = tid >> 4, tn = tid & 15;
    int m0 = tm * 8, n0 = tn * 4;
    int arow = tid >> 2, akq = tid & 3;

    ull acc[8][2];
#pragma unroll
    for (int i = 0; i < 8; i++) { acc[i][0] = 0ull; acc[i][1] = 0ull; }

    float4 aR0, aR1, bR;
    {
        int k0 = 0;
        aR0 = *reinterpret_cast<const float4*>(&g_s2[(bm0 + arow) * 3136 + k0 + akq * 4]);
        aR1 = *reinterpret_cast<const float4*>(&g_s2[(bm0 + arow + 64) * 3136 + k0 + akq * 4]);
        bR  = *reinterpret_cast<const float4*>(&w[(bn0 + arow) * 3136 + k0 + akq * 4]);
    }
    {
        int kb = akq * 4;
        As[0][kb + 0][arow] = aR0.x; As[0][kb + 1][arow] = aR0.y;
        As[0][kb + 2][arow] = aR0.z; As[0][kb + 3][arow] = aR0.w;
        As[0][kb + 0][arow + 64] = aR1.x; As[0][kb + 1][arow + 64] = aR1.y;
        As[0][kb + 2][arow + 64] = aR1.z; As[0][kb + 3][arow + 64] = aR1.w;
        Bs[0][kb + 0][arow] = bR.x; Bs[0][kb + 1][arow] = bR.y;
        Bs[0][kb + 2][arow] = bR.z; Bs[0][kb + 3][arow] = bR.w;
    }
    __syncthreads();

    for (int kt = 0; kt < 196; kt++) {
        int s = kt & 1;
        if (kt < 195) {
            int k0 = (kt + 1) * 16;
            aR0 = *reinterpret_cast<const float4*>(&g_s2[(bm0 + arow) * 3136 + k0 + akq * 4]);
            aR1 = *reinterpret_cast<const float4*>(&g_s2[(bm0 + arow + 64) * 3136 + k0 + akq * 4]);
            bR  = *reinterpret_cast<const float4*>(&w[(bn0 + arow) * 3136 + k0 + akq * 4]);
        }
#pragma unroll
        for (int k = 0; k < 16; k++) {
            float4 a0 = *reinterpret_cast<const float4*>(&As[s][k][m0]);
            float4 a1 = *reinterpret_cast<const float4*>(&As[s][k][m0 + 4]);
            float4 b4 = *reinterpret_cast<const float4*>(&Bs[s][k][n0]);
            ull pb0 = pk2(b4.x, b4.y), pb1 = pk2(b4.z, b4.w);
            ull pa;
            pa = dup2(a0.x); acc[0][0] = ffma2(pa, pb0, acc[0][0]); acc[0][1] = ffma2(pa, pb1, acc[0][1]);
            pa = dup2(a0.y); acc[1][0] = ffma2(pa, pb0, acc[1][0]); acc[1][1] = ffma2(pa, pb1, acc[1][1]);
            pa = dup2(a0.z); acc[2][0] = ffma2(pa, pb0, acc[2][0]); acc[2][1] = ffma2(pa, pb1, acc[2][1]);
            pa = dup2(a0.w); acc[3][0] = ffma2(pa, pb0, acc[3][0]); acc[3][1] = ffma2(pa, pb1, acc[3][1]);
            pa = dup2(a1.x); acc[4][0] = ffma2(pa, pb0, acc[4][0]); acc[4][1] = ffma2(pa, pb1, acc[4][1]);
            pa = dup2(a1.y); acc[5][0] = ffma2(pa, pb0, acc[5][0]); acc[5][1] = ffma2(pa, pb1, acc[5][1]);
            pa = dup2(a1.z); acc[6][0] = ffma2(pa, pb0, acc[6][0]); acc[6][1] = ffma2(pa, pb1, acc[6][1]);
            pa = dup2(a1.w); acc[7][0] = ffma2(pa, pb0, acc[7][0]); acc[7][1] = ffma2(pa, pb1, acc[7][1]);
        }
        if (kt < 195) {
            int ns = 1 - s;
            int kb = akq * 4;
            As[ns][kb + 0][arow] = aR0.x; As[ns][kb + 1][arow] = aR0.y;
            As[ns][kb + 2][arow] = aR0.z; As[ns][kb + 3][arow] = aR0.w;
            As[ns][kb + 0][arow + 64] = aR1.x; As[ns][kb + 1][arow + 64] = aR1.y;
            As[ns][kb + 2][arow + 64] = aR1.z; As[ns][kb + 3][arow + 64] = aR1.w;
            Bs[ns][kb + 0][arow] = bR.x; Bs[ns][kb + 1][arow] = bR.y;
            Bs[ns][kb + 2][arow] = bR.z; Bs[ns][kb + 3][arow] = bR.w;
            __syncthreads();
        }
    }

#pragma unroll
    for (int i = 0; i < 8; i++) {
        int m = bm0 + m0 + i, gn = bn0 + n0;
        float r0, r1, r2, r3;
        upk2(acc[i][0], r0, r1);
        upk2(acc[i][1], r2, r3);
        float4 o;
        o.x = fmaxf(r0 + b[gn + 0], 0.f);
        o.y = fmaxf(r1 + b[gn + 1], 0.f);
        o.z = fmaxf(r2 + b[gn + 2], 0.f);
        o.w = fmaxf(r3 + b[gn + 3], 0.f);
        *reinterpret_cast<float4*>(&g_fc1[m * 1024 + gn]) = o;
    }
}

// ============================================================================
// fc2: [2048,1024] x [10,1024]^T + b. Warp per row.
// ============================================================================
__global__ void __launch_bounds__(256) k_fc2(const float* __restrict__ w,
                                             const float* __restrict__ b,
                                             float* __restrict__ out) {
    int warp = threadIdx.x >> 5, lane = threadIdx.x & 31;
    int row = blockIdx.x * 8 + warp;
    const float* a = &g_fc1[row * 1024];
    float acc[10];
#pragma unroll
    for (int n = 0; n < 10; n++) acc[n] = 0.f;
    for (int k = lane; k < 1024; k += 32) {
        float av = a[k];
#pragma unroll
        for (int n = 0; n < 10; n++) acc[n] += av * w[n * 1024 + k];
    }
#pragma unroll
    for (int n = 0; n < 10; n++)
#pragma unroll
        for (int off = 16; off > 0; off >>= 1)
            acc[n] += __shfl_xor_sync(0xffffffffu, acc[n], off);
    if (lane == 0) {
#pragma unroll
        for (int n = 0; n < 10; n++) out[row * 10 + n] = acc[n] + b[n];
    }
}

// ============================================================================
extern "C" void kernel_launch(void* const* d_in, const int* in_sizes, int n_in,
                              void* d_out, int out_size) {
    const float* x       = (const float*)d_in[0];
    const float* conv1_w = (const float*)d_in[1];
    const float* trelu_t = (const float*)d_in[2];
    const float* conv2_w = (const float*)d_in[3];
    const float* conv2_b = (const float*)d_in[4];
    const float* fc1_w   = (const float*)d_in[5];
    const float* fc1_b   = (const float*)d_in[6];
    const float* fc2_w   = (const float*)d_in[7];
    const float* fc2_b   = (const float*)d_in[8];
    float* out = (float*)d_out;

    const int SMEM2 = (2 * 10368 + 2 * 1600) * 4;  // 95744 B
    cudaFuncSetAttribute(k_conv2, cudaFuncAttributeMaxDynamicSharedMemorySize, SMEM2);

    k_prep<<<(64 * 32 * 25 + 255) / 256, 256>>>(conv2_w);
    k_conv1<<<1024, 392>>>(x, conv1_w, trelu_t);
    k_conv2<<<1024, 392, SMEM2>>>(conv2_b);
    k_fc1<<<dim3(16, 16), 256>>>(fc1_w, fc1_b);
    k_fc2<<<256, 256>>>(fc2_w, fc2_b, out);
}

// round 6
// speedup vs baseline: 1.7895x; 1.7867x over previous
#include <cuda_runtime.h>
#include <cuda_bf16.h>
#include <cstdint>

typedef unsigned long long ull;
typedef unsigned short u16;
typedef unsigned int u32;

// ---------------- device scratch (static, zero-initialized) ----------------
__device__ __align__(16) u16   g_s1h[2048 * 18 * 18 * 32];  // conv1 out NHWC bf16 hi, halo 2 (halo stays 0)
__device__ __align__(16) u16   g_s1l[2048 * 18 * 18 * 32];  // conv1 out bf16 lo
__device__ __align__(16) float g_s2[2048 * 3136];           // conv2 pooled out [b][q*64+co]
__device__ __align__(16) float g_fc1[2048 * 1024];          // fc1 out
__device__ __align__(16) float g_fc1wt[1024 * 3136];        // fc1 w, K reordered to (q,co)
__device__ __align__(16) u16   g_w2b[5 * 2 * 64 * 168];     // conv2 B [dy][plane hi/lo][n=64][k pad 168]

// ---------------- f32x2 helpers ----------------
__device__ __forceinline__ ull ffma2(ull a, ull b, ull c) {
    ull d; asm("fma.rn.f32x2 %0, %1, %2, %3;" : "=l"(d) : "l"(a), "l"(b), "l"(c)); return d;
}
__device__ __forceinline__ ull dup2(float v) {
    ull d; asm("mov.b64 %0, {%1, %1};" : "=l"(d) : "f"(v)); return d;
}
__device__ __forceinline__ ull pk2(float lo, float hi) {
    ull d; asm("mov.b64 %0, {%1, %2};" : "=l"(d) : "f"(lo), "f"(hi)); return d;
}
__device__ __forceinline__ void upk2(ull v, float& lo, float& hi) {
    asm("mov.b64 {%0, %1}, %2;" : "=f"(lo), "=f"(hi) : "l"(v));
}

// ---------------- cp.async ----------------
__device__ __forceinline__ void cp16u(u32 saddr, const void* g) {
    asm volatile("cp.async.ca.shared.global [%0], [%1], 16;" :: "r"(saddr), "l"(g));
}
__device__ __forceinline__ void cp_commit() { asm volatile("cp.async.commit_group;"); }
__device__ __forceinline__ void cp_wait0()  { asm volatile("cp.async.wait_group 0;"); }
__device__ __forceinline__ void cp_wait1()  { asm volatile("cp.async.wait_group 1;"); }

// ---------------- mma.sync / ldmatrix (base sm_103 features) ----------------
__device__ __forceinline__ void ldsm4(u32& r0, u32& r1, u32& r2, u32& r3, u32 addr) {
    asm volatile("ldmatrix.sync.aligned.m8n8.x4.shared.b16 {%0,%1,%2,%3}, [%4];"
                 : "=r"(r0), "=r"(r1), "=r"(r2), "=r"(r3) : "r"(addr));
}
__device__ __forceinline__ void mma16816(float* d, const u32* a, const u32* b) {
    asm volatile("mma.sync.aligned.m16n8k16.row.col.f32.bf16.bf16.f32 "
                 "{%0,%1,%2,%3}, {%4,%5,%6,%7}, {%8,%9}, {%0,%1,%2,%3};"
                 : "+f"(d[0]), "+f"(d[1]), "+f"(d[2]), "+f"(d[3])
                 : "r"(a[0]), "r"(a[1]), "r"(a[2]), "r"(a[3]), "r"(b[0]), "r"(b[1]));
}

__device__ __forceinline__ void ins4(float& a, float& b, float& c, float& d, float v) {
    if (v > d) {
        d = v;
        if (d > c) { float t = c; c = d; d = t;
            if (c > b) { t = b; b = c; c = t;
                if (b > a) { t = a; a = b; b = t; }
            }
        }
    }
}

// ============================================================================
// prep: conv2 B images [dy][plane][n=64][k pad 168], k = dx*32+ci, bf16 hi/lo
// ============================================================================
__global__ void k_prep_w2b(const float* __restrict__ w2) {
    int i = blockIdx.x * blockDim.x + threadIdx.x;
    if (i >= 5 * 2 * 64 * 168) return;
    int dy = i / 21504, r = i % 21504;
    int plane = r / 10752, r2 = r % 10752;
    int co = r2 / 168, k = r2 % 168;
    float v = 0.f;
    if (k < 160) {
        int dx = k >> 5, ci = k & 31;
        v = w2[(co * 32 + ci) * 25 + dy * 5 + dx];
    }
    __nv_bfloat16 h = __float2bfloat16(v);
    if (plane == 0) {
        g_w2b[i] = reinterpret_cast<u16&>(h);
    } else {
        __nv_bfloat16 l2 = __float2bfloat16(v - __bfloat162float(h));
        g_w2b[i] = reinterpret_cast<u16&>(l2);
    }
}

// ============================================================================
// prep: fc1 weight K-permutation  (k = co*49+q) -> (j = q*64+co)
// ============================================================================
__global__ void __launch_bounds__(256) k_prep_fc1w(const float* __restrict__ w) {
    __shared__ float row[3136];
    int n = blockIdx.x;
    for (int i = threadIdx.x; i < 3136; i += 256) row[i] = w[n * 3136 + i];
    __syncthreads();
    for (int i = threadIdx.x; i < 3136; i += 256) {
        int q = i >> 6, co = i & 63;
        g_fc1wt[n * 3136 + i] = row[co * 49 + q];
    }
}

// ============================================================================
// conv1 (1->32, 5x5, pad2) + top-4 mask + threshold ReLU + 2x2 maxpool
// output NHWC bf16 hi/lo with 2-pixel halo (halo stays zero)
// ============================================================================
__global__ void __launch_bounds__(392) k_conv1(const float* __restrict__ xin,
                                               const float* __restrict__ w1,
                                               const float* __restrict__ tt) {
    __shared__ float s_in[2][1024];
    __shared__ ull   s_w[800];
    __shared__ float s_t[32];

    int tid = threadIdx.x;
    int img0 = blockIdx.x * 2;

    for (int i = tid; i < 800; i += 392) { float v = w1[i]; s_w[i] = dup2(v); }
    if (tid < 32) s_t[tid] = tt[tid];
    for (int i = tid; i < 2048; i += 392) ((float*)s_in)[i] = 0.f;
    __syncthreads();
    for (int i = tid; i < 1568; i += 392) {
        int im = i / 784, p = i % 784, y = p / 28, xx = p % 28;
        s_in[im][(y + 2) * 32 + xx + 2] = xin[(img0 + im) * 784 + p];
    }
    __syncthreads();

    int im = tid / 196, t = tid % 196;
    int py = t / 14, px = t % 14;
    const float* base = &s_in[im][(2 * py) * 32 + 2 * px];

    float win[6][6];
#pragma unroll
    for (int r = 0; r < 6; r++)
#pragma unroll
        for (int c = 0; c < 6; c++) win[r][c] = base[r * 32 + c];
    ull pr[30];
#pragma unroll
    for (int dy = 0; dy < 5; dy++)
#pragma unroll
        for (int c = 0; c < 6; c++) pr[dy * 6 + c] = pk2(win[dy][c], win[dy + 1][c]);

    float a0t = -3.4e38f, b0t = -3.4e38f, c0t = -3.4e38f, d0t = -3.4e38f;
    float a1t = -3.4e38f, b1t = -3.4e38f, c1t = -3.4e38f, d1t = -3.4e38f;
    float a2t = -3.4e38f, b2t = -3.4e38f, c2t = -3.4e38f, d2t = -3.4e38f;
    float a3t = -3.4e38f, b3t = -3.4e38f, c3t = -3.4e38f, d3t = -3.4e38f;

    for (int c = 0; c < 32; c++) {
        const ull* wc = &s_w[c * 25];
        ull A0 = 0ull, A1 = 0ull;
#pragma unroll
        for (int dy = 0; dy < 5; dy++)
#pragma unroll
            for (int dx = 0; dx < 5; dx++) {
                ull wv = wc[dy * 5 + dx];
                A0 = ffma2(pr[dy * 6 + dx], wv, A0);
                A1 = ffma2(pr[dy * 6 + dx + 1], wv, A1);
            }
        float v00, v10, v01, v11;
        upk2(A0, v00, v10); upk2(A1, v01, v11);
        ins4(a0t, b0t, c0t, d0t, v00);
        ins4(a1t, b1t, c1t, d1t, v10);
        ins4(a2t, b2t, c2t, d2t, v01);
        ins4(a3t, b3t, c3t, d3t, v11);
    }
    float k0 = d0t, k1 = d1t, k2 = d2t, k3 = d3t;

    int img = img0 + im;
    __align__(16) u16 oh[32], ol[32];
    for (int c = 0; c < 32; c++) {
        const ull* wc = &s_w[c * 25];
        ull A0 = 0ull, A1 = 0ull;
#pragma unroll
        for (int dy = 0; dy < 5; dy++)
#pragma unroll
            for (int dx = 0; dx < 5; dx++) {
                ull wv = wc[dy * 5 + dx];
                A0 = ffma2(pr[dy * 6 + dx], wv, A0);
                A1 = ffma2(pr[dy * 6 + dx + 1], wv, A1);
            }
        float v00, v10, v01, v11;
        upk2(A0, v00, v10); upk2(A1, v01, v11);
        float tc = s_t[c];
        float r0 = (v00 >= k0) ? fmaxf(v00 - tc, 0.f) : 0.f;
        float r1 = (v10 >= k1) ? fmaxf(v10 - tc, 0.f) : 0.f;
        float r2 = (v01 >= k2) ? fmaxf(v01 - tc, 0.f) : 0.f;
        float r3 = (v11 >= k3) ? fmaxf(v11 - tc, 0.f) : 0.f;
        float v = fmaxf(fmaxf(r0, r1), fmaxf(r2, r3));
        __nv_bfloat16 h = __float2bfloat16(v);
        oh[c] = reinterpret_cast<u16&>(h);
        __nv_bfloat16 l2 = __float2bfloat16(v - __bfloat162float(h));
        ol[c] = reinterpret_cast<u16&>(l2);
    }
    size_t ob = (((size_t)img * 18 + (py + 2)) * 18 + (px + 2)) * 32;
#pragma unroll
    for (int c8 = 0; c8 < 4; c8++) {
        *reinterpret_cast<uint4*>(g_s1h + ob + c8 * 8) = *reinterpret_cast<uint4*>(&oh[c8 * 8]);
        *reinterpret_cast<uint4*>(g_s1l + ob + c8 * 8) = *reinterpret_cast<uint4*>(&ol[c8 * 8]);
    }
}

// ============================================================================
// conv2 via mma.sync (bf16 hi/lo x3 terms): 5 accumulated GEMMs, K=160 per dy.
// CTA = 128 threads / 4 warps; warp = 32 M rows (2 m16 tiles), N = 64.
// A fragments loaded straight from gmem (contiguous im2col row spans).
// B staged in smem [plane][n][168] rows (336B rows), cp.async double-buffered.
// Epilogue: shfl quad max-pool + bias + relu -> g_s2[b][q*64+co].
// ============================================================================
__global__ void __launch_bounds__(128) k_conv2(const float* __restrict__ b2) {
    extern __shared__ __align__(16) char sm2[];
    u32 sB = (u32)__cvta_generic_to_shared(sm2);   // 2 x 43008 B buffers

    const int tid = threadIdx.x;
    const int warp = tid >> 5, lane = tid & 31;

    // 4 A-row base offsets (elements): i=0 row lane/4 (mtile0), 1:+8, 2:+16, 3:+24
    u32 off[4];
#pragma unroll
    for (int i = 0; i < 4; i++) {
        int r = warp * 32 + ((i & 1) << 3) + ((i >> 1) << 4) + (lane >> 2);
        int m = blockIdx.x * 128 + r;
        int g = m >> 2, j = m & 3;
        int b = g / 49, q = g % 49;
        int qy = q / 7, qx = q % 7;
        int py = 2 * qy + (j >> 1), px = 2 * qx + (j & 1);
        off[i] = (u32)(((b * 18 + py) * 18 + px) * 32);
    }
    const u16* __restrict__ ph = g_s1h;
    const u16* __restrict__ pl = g_s1l;

    // preload B(dy=0) into buf0: 43008 B
    for (int i = tid; i < 2688; i += 128)
        cp16u(sB + (u32)i * 16u, (const char*)g_w2b + (size_t)i * 16);
    cp_commit();

    float d[2][8][4];
#pragma unroll
    for (int mt = 0; mt < 2; mt++)
#pragma unroll
        for (int nt = 0; nt < 8; nt++)
#pragma unroll
            for (int e = 0; e < 4; e++) d[mt][nt][e] = 0.f;

    const u32 kb2 = (u32)(lane & 3) * 2u;                      // A elem offset
    const u32 lrow = (u32)((lane & 7) + ((lane >> 4) << 3));   // ldmatrix row
    const u32 lkb16 = (u32)(((lane >> 3) & 1) << 4);           // ldmatrix k half (bytes)

    for (int dy = 0; dy < 5; dy++) {
        if (dy < 4) {   // prefetch B(dy+1) into the other buffer
            u32 dst = sB + (u32)((dy + 1) & 1) * 43008u;
            const char* src = (const char*)g_w2b + (size_t)(dy + 1) * 43008u;
            for (int i = tid; i < 2688; i += 128)
                cp16u(dst + (u32)i * 16u, src + (size_t)i * 16);
            cp_commit();
            cp_wait1();
        } else {
            cp_wait0();
        }
        __syncthreads();

        const u32 dyoff = (u32)dy * (18 * 32);
        const u32 bb = sB + (u32)(dy & 1) * 43008u;   // hi plane; lo plane = +21504 B

#pragma unroll
        for (int s = 0; s < 10; s++) {
            u32 ah[2][4], al[2][4];
#pragma unroll
            for (int mt = 0; mt < 2; mt++) {
                u32 i0 = off[mt * 2]     + dyoff + (u32)s * 16u + kb2;
                u32 i1 = off[mt * 2 + 1] + dyoff + (u32)s * 16u + kb2;
                ah[mt][0] = *reinterpret_cast<const u32*>(ph + i0);
                ah[mt][1] = *reinterpret_cast<const u32*>(ph + i1);
                ah[mt][2] = *reinterpret_cast<const u32*>(ph + i0 + 8);
                ah[mt][3] = *reinterpret_cast<const u32*>(ph + i1 + 8);
                al[mt][0] = *reinterpret_cast<const u32*>(pl + i0);
                al[mt][1] = *reinterpret_cast<const u32*>(pl + i1);
                al[mt][2] = *reinterpret_cast<const u32*>(pl + i0 + 8);
                al[mt][3] = *reinterpret_cast<const u32*>(pl + i1 + 8);
            }
            u32 bh[8][2], bl[8][2];
#pragma unroll
            for (int p = 0; p < 4; p++) {
                u32 ad = bb + ((u32)p * 16u + lrow) * 336u + (u32)s * 32u + lkb16;
                ldsm4(bh[2 * p][0], bh[2 * p][1], bh[2 * p + 1][0], bh[2 * p + 1][1], ad);
                ldsm4(bl[2 * p][0], bl[2 * p][1], bl[2 * p + 1][0], bl[2 * p + 1][1],
                      ad + 21504u);   // lo plane stride = 64*168*2 B
            }
#pragma unroll
            for (int mt = 0; mt < 2; mt++)
#pragma unroll
                for (int nt = 0; nt < 8; nt++) mma16816(d[mt][nt], ah[mt], bh[nt]);
#pragma unroll
            for (int mt = 0; mt < 2; mt++)
#pragma unroll
                for (int nt = 0; nt < 8; nt++) mma16816(d[mt][nt], al[mt], bh[nt]);
#pragma unroll
            for (int mt = 0; mt < 2; mt++)
#pragma unroll
                for (int nt = 0; nt < 8; nt++) mma16816(d[mt][nt], ah[mt], bl[nt]);
        }
        __syncthreads();
    }

    // epilogue: quad max-pool (shfl over member lanes) + bias + relu + store
    float bA[8], bB[8];
#pragma unroll
    for (int nt = 0; nt < 8; nt++) {
        int co = nt * 8 + 2 * (lane & 3);
        bA[nt] = b2[co]; bB[nt] = b2[co + 1];
    }
    bool act = ((lane & 12) == 0);
#pragma unroll
    for (int mt = 0; mt < 2; mt++)
#pragma unroll
        for (int rp = 0; rp < 2; rp++) {
            int G = blockIdx.x * 32 + warp * 8 + mt * 4 + rp * 2 + (lane >> 4);
            int b_ = G / 49, q_ = G % 49;
            float* op = g_s2 + (size_t)b_ * 3136 + q_ * 64;
#pragma unroll
            for (int nt = 0; nt < 8; nt++) {
                float v0 = d[mt][nt][2 * rp];
                float v1 = d[mt][nt][2 * rp + 1];
                v0 = fmaxf(v0, __shfl_xor_sync(0xffffffffu, v0, 4));
                v0 = fmaxf(v0, __shfl_xor_sync(0xffffffffu, v0, 8));
                v1 = fmaxf(v1, __shfl_xor_sync(0xffffffffu, v1, 4));
                v1 = fmaxf(v1, __shfl_xor_sync(0xffffffffu, v1, 8));
                if (act) {
                    float2 o;
                    o.x = fmaxf(v0 + bA[nt], 0.f);
                    o.y = fmaxf(v1 + bB[nt], 0.f);
                    *reinterpret_cast<float2*>(op + nt * 8 + 2 * (lane & 3)) = o;
                }
            }
        }
}

// ============================================================================
// fc1: g_s2[2048,3136] x g_fc1wt[1024,3136]^T + b, relu. f32x2 tiled GEMM.
// ============================================================================
__global__ void __launch_bounds__(256) k_fc1(const float* __restrict__ b) {
    __shared__ __align__(16) float As[2][16][132];
    __shared__ __align__(16) float Bs[2][16][68];

    int tid = threadIdx.x;
    int bm0 = blockIdx.x * 128, bn0 = blockIdx.y * 64;
    int tm = tid >> 4, tn = tid & 15;
    int m0 = tm * 8, n0 = tn * 4;
    int arow = tid >> 2, akq = tid & 3;

    ull acc[8][2];
#pragma unroll
    for (int i = 0; i < 8; i++) { acc[i][0] = 0ull; acc[i][1] = 0ull; }

    float4 aR0, aR1, bR;
    aR0 = *reinterpret_cast<const float4*>(&g_s2[(bm0 + arow) * 3136 + akq * 4]);
    aR1 = *reinterpret_cast<const float4*>(&g_s2[(bm0 + arow + 64) * 3136 + akq * 4]);
    bR  = *reinterpret_cast<const float4*>(&g_fc1wt[(bn0 + arow) * 3136 + akq * 4]);
    {
        int kb = akq * 4;
        As[0][kb + 0][arow] = aR0.x; As[0][kb + 1][arow] = aR0.y;
        As[0][kb + 2][arow] = aR0.z; As[0][kb + 3][arow] = aR0.w;
        As[0][kb + 0][arow + 64] = aR1.x; As[0][kb + 1][arow + 64] = aR1.y;
        As[0][kb + 2][arow + 64] = aR1.z; As[0][kb + 3][arow + 64] = aR1.w;
        Bs[0][kb + 0][arow] = bR.x; Bs[0][kb + 1][arow] = bR.y;
        Bs[0][kb + 2][arow] = bR.z; Bs[0][kb + 3][arow] = bR.w;
    }
    __syncthreads();

    for (int kt = 0; kt < 196; kt++) {
        int s = kt & 1;
        if (kt < 195) {
            int k0 = (kt + 1) * 16;
            aR0 = *reinterpret_cast<const float4*>(&g_s2[(bm0 + arow) * 3136 + k0 + akq * 4]);
            aR1 = *reinterpret_cast<const float4*>(&g_s2[(bm0 + arow + 64) * 3136 + k0 + akq * 4]);
            bR  = *reinterpret_cast<const float4*>(&g_fc1wt[(bn0 + arow) * 3136 + k0 + akq * 4]);
        }
#pragma unroll
        for (int k = 0; k < 16; k++) {
            float4 a0 = *reinterpret_cast<const float4*>(&As[s][k][m0]);
            float4 a1 = *reinterpret_cast<const float4*>(&As[s][k][m0 + 4]);
            float4 b4 = *reinterpret_cast<const float4*>(&Bs[s][k][n0]);
            ull pb0 = pk2(b4.x, b4.y), pb1 = pk2(b4.z, b4.w);
            ull pa;
            pa = dup2(a0.x); acc[0][0] = ffma2(pa, pb0, acc[0][0]); acc[0][1] = ffma2(pa, pb1, acc[0][1]);
            pa = dup2(a0.y); acc[1][0] = ffma2(pa, pb0, acc[1][0]); acc[1][1] = ffma2(pa, pb1, acc[1][1]);
            pa = dup2(a0.z); acc[2][0] = ffma2(pa, pb0, acc[2][0]); acc[2][1] = ffma2(pa, pb1, acc[2][1]);
            pa = dup2(a0.w); acc[3][0] = ffma2(pa, pb0, acc[3][0]); acc[3][1] = ffma2(pa, pb1, acc[3][1]);
            pa = dup2(a1.x); acc[4][0] = ffma2(pa, pb0, acc[4][0]); acc[4][1] = ffma2(pa, pb1, acc[4][1]);
            pa = dup2(a1.y); acc[5][0] = ffma2(pa, pb0, acc[5][0]); acc[5][1] = ffma2(pa, pb1, acc[5][1]);
            pa = dup2(a1.z); acc[6][0] = ffma2(pa, pb0, acc[6][0]); acc[6][1] = ffma2(pa, pb1, acc[6][1]);
            pa = dup2(a1.w); acc[7][0] = ffma2(pa, pb0, acc[7][0]); acc[7][1] = ffma2(pa, pb1, acc[7][1]);
        }
        if (kt < 195) {
            int ns = 1 - s;
            int kb = akq * 4;
            As[ns][kb + 0][arow] = aR0.x; As[ns][kb + 1][arow] = aR0.y;
            As[ns][kb + 2][arow] = aR0.z; As[ns][kb + 3][arow] = aR0.w;
            As[ns][kb + 0][arow + 64] = aR1.x; As[ns][kb + 1][arow + 64] = aR1.y;
            As[ns][kb + 2][arow + 64] = aR1.z; As[ns][kb + 3][arow + 64] = aR1.w;
            Bs[ns][kb + 0][arow] = bR.x; Bs[ns][kb + 1][arow] = bR.y;
            Bs[ns][kb + 2][arow] = bR.z; Bs[ns][kb + 3][arow] = bR.w;
            __syncthreads();
        }
    }

#pragma unroll
    for (int i = 0; i < 8; i++) {
        int m = bm0 + m0 + i, gn = bn0 + n0;
        float r0, r1, r2, r3;
        upk2(acc[i][0], r0, r1);
        upk2(acc[i][1], r2, r3);
        float4 o;
        o.x = fmaxf(r0 + b[gn + 0], 0.f);
        o.y = fmaxf(r1 + b[gn + 1], 0.f);
        o.z = fmaxf(r2 + b[gn + 2], 0.f);
        o.w = fmaxf(r3 + b[gn + 3], 0.f);
        *reinterpret_cast<float4*>(&g_fc1[m * 1024 + gn]) = o;
    }
}

// ============================================================================
// fc2: [2048,1024] x [10,1024]^T + b. Warp per row.
// ============================================================================
__global__ void __launch_bounds__(256) k_fc2(const float* __restrict__ w,
                                             const float* __restrict__ b,
                                             float* __restrict__ out) {
    int warp = threadIdx.x >> 5, lane = threadIdx.x & 31;
    int row = blockIdx.x * 8 + warp;
    const float* a = &g_fc1[row * 1024];
    float acc[10];
#pragma unroll
    for (int n = 0; n < 10; n++) acc[n] = 0.f;
    for (int k = lane; k < 1024; k += 32) {
        float av = a[k];
#pragma unroll
        for (int n = 0; n < 10; n++) acc[n] += av * w[n * 1024 + k];
    }
#pragma unroll
    for (int n = 0; n < 10; n++)
#pragma unroll
        for (int off = 16; off > 0; off >>= 1)
            acc[n] += __shfl_xor_sync(0xffffffffu, acc[n], off);
    if (lane == 0) {
#pragma unroll
        for (int n = 0; n < 10; n++) out[row * 10 + n] = acc[n] + b[n];
    }
}

// ============================================================================
extern "C" void kernel_launch(void* const* d_in, const int* in_sizes, int n_in,
                              void* d_out, int out_size) {
    const float* x       = (const float*)d_in[0];
    const float* conv1_w = (const float*)d_in[1];
    const float* trelu_t = (const float*)d_in[2];
    const float* conv2_w = (const float*)d_in[3];
    const float* conv2_b = (const float*)d_in[4];
    const float* fc1_w   = (const float*)d_in[5];
    const float* fc1_b   = (const float*)d_in[6];
    const float* fc2_w   = (const float*)d_in[7];
    const float* fc2_b   = (const float*)d_in[8];
    float* out = (float*)d_out;

    const int SMEM2 = 2 * 43008;   // B double buffer
    cudaFuncSetAttribute(k_conv2, cudaFuncAttributeMaxDynamicSharedMemorySize, SMEM2);

    k_prep_w2b<<<(5 * 2 * 64 * 168 + 255) / 256, 256>>>(conv2_w);
    k_prep_fc1w<<<1024, 256>>>(fc1_w);
    k_conv1<<<1024, 392>>>(x, conv1_w, trelu_t);
    k_conv2<<<3136, 128, SMEM2>>>(conv2_b);
    k_fc1<<<dim3(16, 16), 256>>>(fc1_b);
    k_fc2<<<256, 256>>>(fc2_w, fc2_b, out);
}

// round 7
// speedup vs baseline: 1.8926x; 1.0576x over previous
#include <cuda_runtime.h>
#include <cuda_bf16.h>
#include <cstdint>

typedef unsigned long long ull;
typedef unsigned short u16;
typedef unsigned int u32;

// ---------------- device scratch (static, zero-initialized) ----------------
__device__ __align__(16) u16   g_s1h[2048 * 18 * 18 * 32];  // conv1 out NHWC bf16 hi, halo 2
__device__ __align__(16) u16   g_s1l[2048 * 18 * 18 * 32];  // conv1 out bf16 lo
__device__ __align__(16) u16   g_s2h[2048 * 3136];          // conv2 pooled out bf16 hi [b][q*64+co]
__device__ __align__(16) u16   g_s2l[2048 * 3136];          // conv2 pooled out bf16 lo
__device__ __align__(16) float g_fc1[2048 * 1024];          // fc1 out (f32)
__device__ __align__(16) u16   g_fc1wh[1024 * 3136];        // fc1 w bf16 hi, K reordered (q,co)
__device__ __align__(16) u16   g_fc1wl[1024 * 3136];        // fc1 w bf16 lo
__device__ __align__(16) u16   g_w2b[5 * 2 * 64 * 168];     // conv2 B [dy][plane][n=64][k pad 168]

// ---------------- f32x2 helpers ----------------
__device__ __forceinline__ ull ffma2(ull a, ull b, ull c) {
    ull d; asm("fma.rn.f32x2 %0, %1, %2, %3;" : "=l"(d) : "l"(a), "l"(b), "l"(c)); return d;
}
__device__ __forceinline__ ull dup2(float v) {
    ull d; asm("mov.b64 %0, {%1, %1};" : "=l"(d) : "f"(v)); return d;
}
__device__ __forceinline__ ull pk2(float lo, float hi) {
    ull d; asm("mov.b64 %0, {%1, %2};" : "=l"(d) : "f"(lo), "f"(hi)); return d;
}
__device__ __forceinline__ void upk2(ull v, float& lo, float& hi) {
    asm("mov.b64 {%0, %1}, %2;" : "=f"(lo), "=f"(hi) : "l"(v));
}

// ---------------- cp.async ----------------
__device__ __forceinline__ void cp16u(u32 saddr, const void* g) {
    asm volatile("cp.async.ca.shared.global [%0], [%1], 16;" :: "r"(saddr), "l"(g));
}
__device__ __forceinline__ void cp_commit() { asm volatile("cp.async.commit_group;"); }
__device__ __forceinline__ void cp_wait0()  { asm volatile("cp.async.wait_group 0;"); }
__device__ __forceinline__ void cp_wait1()  { asm volatile("cp.async.wait_group 1;"); }

// ---------------- mma.sync / ldmatrix (base sm_103 features) ----------------
__device__ __forceinline__ void ldsm4(u32& r0, u32& r1, u32& r2, u32& r3, u32 addr) {
    asm volatile("ldmatrix.sync.aligned.m8n8.x4.shared.b16 {%0,%1,%2,%3}, [%4];"
                 : "=r"(r0), "=r"(r1), "=r"(r2), "=r"(r3) : "r"(addr));
}
__device__ __forceinline__ void mma16816(float* d, const u32* a, const u32* b) {
    asm volatile("mma.sync.aligned.m16n8k16.row.col.f32.bf16.bf16.f32 "
                 "{%0,%1,%2,%3}, {%4,%5,%6,%7}, {%8,%9}, {%0,%1,%2,%3};"
                 : "+f"(d[0]), "+f"(d[1]), "+f"(d[2]), "+f"(d[3])
                 : "r"(a[0]), "r"(a[1]), "r"(a[2]), "r"(a[3]), "r"(b[0]), "r"(b[1]));
}

__device__ __forceinline__ void ins4(float& a, float& b, float& c, float& d, float v) {
    if (v > d) {
        d = v;
        if (d > c) { float t = c; c = d; d = t;
            if (c > b) { t = b; b = c; c = t;
                if (b > a) { t = a; a = b; b = t; }
            }
        }
    }
}
__device__ __forceinline__ u32 bf16pack2(float x, float y) {
    __nv_bfloat16 hx = __float2bfloat16(x), hy = __float2bfloat16(y);
    return (u32)reinterpret_cast<u16&>(hx) | ((u32)reinterpret_cast<u16&>(hy) << 16);
}

// ============================================================================
// prep: conv2 B images [dy][plane][n=64][k pad 168], k = dx*32+ci, bf16 hi/lo
// ============================================================================
__global__ void k_prep_w2b(const float* __restrict__ w2) {
    int i = blockIdx.x * blockDim.x + threadIdx.x;
    if (i >= 5 * 2 * 64 * 168) return;
    int dy = i / 21504, r = i % 21504;
    int plane = r / 10752, r2 = r % 10752;
    int co = r2 / 168, k = r2 % 168;
    float v = 0.f;
    if (k < 160) {
        int dx = k >> 5, ci = k & 31;
        v = w2[(co * 32 + ci) * 25 + dy * 5 + dx];
    }
    __nv_bfloat16 h = __float2bfloat16(v);
    if (plane == 0) {
        g_w2b[i] = reinterpret_cast<u16&>(h);
    } else {
        __nv_bfloat16 l2 = __float2bfloat16(v - __bfloat162float(h));
        g_w2b[i] = reinterpret_cast<u16&>(l2);
    }
}

// ============================================================================
// prep: fc1 weight K-permute (k = co*49+q -> j = q*64+co) + bf16 hi/lo split
// ============================================================================
__global__ void __launch_bounds__(256) k_prep_fc1w(const float* __restrict__ w) {
    __shared__ float row[3136];
    int n = blockIdx.x;
    for (int i = threadIdx.x; i < 3136; i += 256) row[i] = w[n * 3136 + i];
    __syncthreads();
    for (int i = threadIdx.x; i < 3136; i += 256) {
        int q = i >> 6, co = i & 63;
        float v = row[co * 49 + q];
        __nv_bfloat16 h = __float2bfloat16(v);
        __nv_bfloat16 l2 = __float2bfloat16(v - __bfloat162float(h));
        g_fc1wh[n * 3136 + i] = reinterpret_cast<u16&>(h);
        g_fc1wl[n * 3136 + i] = reinterpret_cast<u16&>(l2);
    }
}

// ============================================================================
// conv1 (1->32, 5x5, pad2) + top-4 mask + threshold ReLU + 2x2 maxpool
// output NHWC bf16 hi/lo with 2-pixel halo (halo stays zero)
// ============================================================================
__global__ void __launch_bounds__(392) k_conv1(const float* __restrict__ xin,
                                               const float* __restrict__ w1,
                                               const float* __restrict__ tt) {
    __shared__ float s_in[2][1024];
    __shared__ ull   s_w[800];
    __shared__ float s_t[32];

    int tid = threadIdx.x;
    int img0 = blockIdx.x * 2;

    for (int i = tid; i < 800; i += 392) { float v = w1[i]; s_w[i] = dup2(v); }
    if (tid < 32) s_t[tid] = tt[tid];
    for (int i = tid; i < 2048; i += 392) ((float*)s_in)[i] = 0.f;
    __syncthreads();
    for (int i = tid; i < 1568; i += 392) {
        int im = i / 784, p = i % 784, y = p / 28, xx = p % 28;
        s_in[im][(y + 2) * 32 + xx + 2] = xin[(img0 + im) * 784 + p];
    }
    __syncthreads();

    int im = tid / 196, t = tid % 196;
    int py = t / 14, px = t % 14;
    const float* base = &s_in[im][(2 * py) * 32 + 2 * px];

    float win[6][6];
#pragma unroll
    for (int r = 0; r < 6; r++)
#pragma unroll
        for (int c = 0; c < 6; c++) win[r][c] = base[r * 32 + c];
    ull pr[30];
#pragma unroll
    for (int dy = 0; dy < 5; dy++)
#pragma unroll
        for (int c = 0; c < 6; c++) pr[dy * 6 + c] = pk2(win[dy][c], win[dy + 1][c]);

    float a0t = -3.4e38f, b0t = -3.4e38f, c0t = -3.4e38f, d0t = -3.4e38f;
    float a1t = -3.4e38f, b1t = -3.4e38f, c1t = -3.4e38f, d1t = -3.4e38f;
    float a2t = -3.4e38f, b2t = -3.4e38f, c2t = -3.4e38f, d2t = -3.4e38f;
    float a3t = -3.4e38f, b3t = -3.4e38f, c3t = -3.4e38f, d3t = -3.4e38f;

    for (int c = 0; c < 32; c++) {
        const ull* wc = &s_w[c * 25];
        ull A0 = 0ull, A1 = 0ull;
#pragma unroll
        for (int dy = 0; dy < 5; dy++)
#pragma unroll
            for (int dx = 0; dx < 5; dx++) {
                ull wv = wc[dy * 5 + dx];
                A0 = ffma2(pr[dy * 6 + dx], wv, A0);
                A1 = ffma2(pr[dy * 6 + dx + 1], wv, A1);
            }
        float v00, v10, v01, v11;
        upk2(A0, v00, v10); upk2(A1, v01, v11);
        ins4(a0t, b0t, c0t, d0t, v00);
        ins4(a1t, b1t, c1t, d1t, v10);
        ins4(a2t, b2t, c2t, d2t, v01);
        ins4(a3t, b3t, c3t, d3t, v11);
    }
    float k0 = d0t, k1 = d1t, k2 = d2t, k3 = d3t;

    int img = img0 + im;
    __align__(16) u16 oh[32], ol[32];
    for (int c = 0; c < 32; c++) {
        const ull* wc = &s_w[c * 25];
        ull A0 = 0ull, A1 = 0ull;
#pragma unroll
        for (int dy = 0; dy < 5; dy++)
#pragma unroll
            for (int dx = 0; dx < 5; dx++) {
                ull wv = wc[dy * 5 + dx];
                A0 = ffma2(pr[dy * 6 + dx], wv, A0);
                A1 = ffma2(pr[dy * 6 + dx + 1], wv, A1);
            }
        float v00, v10, v01, v11;
        upk2(A0, v00, v10); upk2(A1, v01, v11);
        float tc = s_t[c];
        float r0 = (v00 >= k0) ? fmaxf(v00 - tc, 0.f) : 0.f;
        float r1 = (v10 >= k1) ? fmaxf(v10 - tc, 0.f) : 0.f;
        float r2 = (v01 >= k2) ? fmaxf(v01 - tc, 0.f) : 0.f;
        float r3 = (v11 >= k3) ? fmaxf(v11 - tc, 0.f) : 0.f;
        float v = fmaxf(fmaxf(r0, r1), fmaxf(r2, r3));
        __nv_bfloat16 h = __float2bfloat16(v);
        oh[c] = reinterpret_cast<u16&>(h);
        __nv_bfloat16 l2 = __float2bfloat16(v - __bfloat162float(h));
        ol[c] = reinterpret_cast<u16&>(l2);
    }
    size_t ob = (((size_t)img * 18 + (py + 2)) * 18 + (px + 2)) * 32;
#pragma unroll
    for (int c8 = 0; c8 < 4; c8++) {
        *reinterpret_cast<uint4*>(g_s1h + ob + c8 * 8) = *reinterpret_cast<uint4*>(&oh[c8 * 8]);
        *reinterpret_cast<uint4*>(g_s1l + ob + c8 * 8) = *reinterpret_cast<uint4*>(&ol[c8 * 8]);
    }
}

// ============================================================================
// conv2 via mma.sync (bf16 hi/lo x3 terms): 5 accumulated GEMMs, K=160 per dy.
// Epilogue: shfl quad max-pool + bias + relu -> bf16 hi/lo g_s2h/g_s2l.
// ============================================================================
__global__ void __launch_bounds__(128) k_conv2(const float* __restrict__ b2) {
    extern __shared__ __align__(16) char sm2[];
    u32 sB = (u32)__cvta_generic_to_shared(sm2);   // 2 x 43008 B buffers

    const int tid = threadIdx.x;
    const int warp = tid >> 5, lane = tid & 31;

    u32 off[4];
#pragma unroll
    for (int i = 0; i < 4; i++) {
        int r = warp * 32 + ((i & 1) << 3) + ((i >> 1) << 4) + (lane >> 2);
        int m = blockIdx.x * 128 + r;
        int g = m >> 2, j = m & 3;
        int b = g / 49, q = g % 49;
        int qy = q / 7, qx = q % 7;
        int py = 2 * qy + (j >> 1), px = 2 * qx + (j & 1);
        off[i] = (u32)(((b * 18 + py) * 18 + px) * 32);
    }
    const u16* __restrict__ ph = g_s1h;
    const u16* __restrict__ pl = g_s1l;

    for (int i = tid; i < 2688; i += 128)
        cp16u(sB + (u32)i * 16u, (const char*)g_w2b + (size_t)i * 16);
    cp_commit();

    float d[2][8][4];
#pragma unroll
    for (int mt = 0; mt < 2; mt++)
#pragma unroll
        for (int nt = 0; nt < 8; nt++)
#pragma unroll
            for (int e = 0; e < 4; e++) d[mt][nt][e] = 0.f;

    const u32 kb2 = (u32)(lane & 3) * 2u;
    const u32 lrow = (u32)((lane & 7) + ((lane >> 4) << 3));
    const u32 lkb16 = (u32)(((lane >> 3) & 1) << 4);

    for (int dy = 0; dy < 5; dy++) {
        if (dy < 4) {
            u32 dst = sB + (u32)((dy + 1) & 1) * 43008u;
            const char* src = (const char*)g_w2b + (size_t)(dy + 1) * 43008u;
            for (int i = tid; i < 2688; i += 128)
                cp16u(dst + (u32)i * 16u, src + (size_t)i * 16);
            cp_commit();
            cp_wait1();
        } else {
            cp_wait0();
        }
        __syncthreads();

        const u32 dyoff = (u32)dy * (18 * 32);
        const u32 bb = sB + (u32)(dy & 1) * 43008u;

#pragma unroll
        for (int s = 0; s < 10; s++) {
            u32 ah[2][4], al[2][4];
#pragma unroll
            for (int mt = 0; mt < 2; mt++) {
                u32 i0 = off[mt * 2]     + dyoff + (u32)s * 16u + kb2;
                u32 i1 = off[mt * 2 + 1] + dyoff + (u32)s * 16u + kb2;
                ah[mt][0] = *reinterpret_cast<const u32*>(ph + i0);
                ah[mt][1] = *reinterpret_cast<const u32*>(ph + i1);
                ah[mt][2] = *reinterpret_cast<const u32*>(ph + i0 + 8);
                ah[mt][3] = *reinterpret_cast<const u32*>(ph + i1 + 8);
                al[mt][0] = *reinterpret_cast<const u32*>(pl + i0);
                al[mt][1] = *reinterpret_cast<const u32*>(pl + i1);
                al[mt][2] = *reinterpret_cast<const u32*>(pl + i0 + 8);
                al[mt][3] = *reinterpret_cast<const u32*>(pl + i1 + 8);
            }
            u32 bh[8][2], bl[8][2];
#pragma unroll
            for (int p = 0; p < 4; p++) {
                u32 ad = bb + ((u32)p * 16u + lrow) * 336u + (u32)s * 32u + lkb16;
                ldsm4(bh[2 * p][0], bh[2 * p][1], bh[2 * p + 1][0], bh[2 * p + 1][1], ad);
                ldsm4(bl[2 * p][0], bl[2 * p][1], bl[2 * p + 1][0], bl[2 * p + 1][1],
                      ad + 21504u);
            }
#pragma unroll
            for (int mt = 0; mt < 2; mt++)
#pragma unroll
                for (int nt = 0; nt < 8; nt++) mma16816(d[mt][nt], ah[mt], bh[nt]);
#pragma unroll
            for (int mt = 0; mt < 2; mt++)
#pragma unroll
                for (int nt = 0; nt < 8; nt++) mma16816(d[mt][nt], al[mt], bh[nt]);
#pragma unroll
            for (int mt = 0; mt < 2; mt++)
#pragma unroll
                for (int nt = 0; nt < 8; nt++) mma16816(d[mt][nt], ah[mt], bl[nt]);
        }
        __syncthreads();
    }

    // epilogue: quad max-pool + bias + relu -> bf16 hi/lo planes
    float bA[8], bB[8];
#pragma unroll
    for (int nt = 0; nt < 8; nt++) {
        int co = nt * 8 + 2 * (lane & 3);
        bA[nt] = b2[co]; bB[nt] = b2[co + 1];
    }
    bool act = ((lane & 12) == 0);
#pragma unroll
    for (int mt = 0; mt < 2; mt++)
#pragma unroll
        for (int rp = 0; rp < 2; rp++) {
            int G = blockIdx.x * 32 + warp * 8 + mt * 4 + rp * 2 + (lane >> 4);
            int b_ = G / 49, q_ = G % 49;
            size_t obase = (size_t)b_ * 3136 + q_ * 64;
#pragma unroll
            for (int nt = 0; nt < 8; nt++) {
                float v0 = d[mt][nt][2 * rp];
                float v1 = d[mt][nt][2 * rp + 1];
                v0 = fmaxf(v0, __shfl_xor_sync(0xffffffffu, v0, 4));
                v0 = fmaxf(v0, __shfl_xor_sync(0xffffffffu, v0, 8));
                v1 = fmaxf(v1, __shfl_xor_sync(0xffffffffu, v1, 4));
                v1 = fmaxf(v1, __shfl_xor_sync(0xffffffffu, v1, 8));
                if (act) {
                    float ox = fmaxf(v0 + bA[nt], 0.f);
                    float oy = fmaxf(v1 + bB[nt], 0.f);
                    __nv_bfloat16 hx = __float2bfloat16(ox), hy = __float2bfloat16(oy);
                    float lx = ox - __bfloat162float(hx);
                    float ly = oy - __bfloat162float(hy);
                    size_t idx = obase + nt * 8 + 2 * (lane & 3);
                    *reinterpret_cast<u32*>(g_s2h + idx) =
                        (u32)reinterpret_cast<u16&>(hx) | ((u32)reinterpret_cast<u16&>(hy) << 16);
                    *reinterpret_cast<u32*>(g_s2l + idx) = bf16pack2(lx, ly);
                }
            }
        }
}

// ============================================================================
// fc1 via mma.sync (bf16 hi/lo x3): M=2048, N=1024, K=3136.
// CTA 256 thr / 8 warps = M128 x N128 tile; warp = m32 x n64.
// K-chunk 32, B double-buffered in smem (80B padded rows, conflict-free
// ldmatrix), A fragments straight from gmem. Epilogue: bias+relu f32.
// ============================================================================
__global__ void __launch_bounds__(256) k_fc1(const float* __restrict__ b) {
    __shared__ __align__(16) u16 sw[2][2][128][40];   // [buf][plane][n][k pad 40]

    const int tid = threadIdx.x;
    const int warp = tid >> 5, lane = tid & 31;
    const int wm = warp >> 1, wn = warp & 1;
    const int bm = blockIdx.x * 128, bn = blockIdx.y * 128;

    const u16* __restrict__ pah = g_s2h;
    const u16* __restrict__ pal = g_s2l;

    u32 rowA[2][2];
#pragma unroll
    for (int mt = 0; mt < 2; mt++) {
        u32 r0 = (u32)(bm + wm * 32 + mt * 16 + (lane >> 2));
        rowA[mt][0] = r0 * 3136u;
        rowA[mt][1] = (r0 + 8u) * 3136u;
    }
    const u32 kq = (u32)(lane & 3) * 2u;
    const u32 lrow = (u32)((lane & 7) + ((lane >> 4) << 3));
    const u32 lkb16 = (u32)(((lane >> 3) & 1) << 4);
    const u32 swbase = (u32)__cvta_generic_to_shared(&sw[0][0][0][0]);

    // chunk loader: 1024 cp16 per chunk (2 planes x 128 rows x 4 sixteens)
    auto load_chunk = [&](int buf, int k0) {
        u32 dstb = swbase + (u32)buf * 20480u;
        for (int i = tid; i < 1024; i += 256) {
            int plane = i >> 9, r = i & 511;
            int row = r >> 2, qh = r & 3;
            const u16* src = (plane ? g_fc1wl : g_fc1wh) + (size_t)(bn + row) * 3136 + k0 + qh * 8;
            cp16u(dstb + (u32)plane * 10240u + (u32)row * 80u + (u32)qh * 16u, src);
        }
    };

    load_chunk(0, 0);
    cp_commit();

    float d[2][8][4];
#pragma unroll
    for (int mt = 0; mt < 2; mt++)
#pragma unroll
        for (int nt = 0; nt < 8; nt++)
#pragma unroll
            for (int e = 0; e < 4; e++) d[mt][nt][e] = 0.f;

    for (int kt = 0; kt < 98; kt++) {
        if (kt < 97) {
            load_chunk((kt + 1) & 1, (kt + 1) * 32);
            cp_commit();
            cp_wait1();
        } else {
            cp_wait0();
        }
        __syncthreads();

        const int k0 = kt * 32;
        // A fragments for both k16 sub-steps, both planes (up-front LDG batch)
        u32 ah[2][2][4], al[2][2][4];
#pragma unroll
        for (int ks = 0; ks < 2; ks++)
#pragma unroll
            for (int mt = 0; mt < 2; mt++) {
                u32 i0 = rowA[mt][0] + (u32)k0 + (u32)ks * 16u + kq;
                u32 i1 = rowA[mt][1] + (u32)k0 + (u32)ks * 16u + kq;
                ah[ks][mt][0] = *reinterpret_cast<const u32*>(pah + i0);
                ah[ks][mt][1] = *reinterpret_cast<const u32*>(pah + i1);
                ah[ks][mt][2] = *reinterpret_cast<const u32*>(pah + i0 + 8);
                ah[ks][mt][3] = *reinterpret_cast<const u32*>(pah + i1 + 8);
                al[ks][mt][0] = *reinterpret_cast<const u32*>(pal + i0);
                al[ks][mt][1] = *reinterpret_cast<const u32*>(pal + i1);
                al[ks][mt][2] = *reinterpret_cast<const u32*>(pal + i0 + 8);
                al[ks][mt][3] = *reinterpret_cast<const u32*>(pal + i1 + 8);
            }

        const u32 bb = swbase + (u32)(kt & 1) * 20480u;
#pragma unroll
        for (int ks = 0; ks < 2; ks++) {
            u32 bh[8][2], bl[8][2];
#pragma unroll
            for (int p = 0; p < 4; p++) {
                u32 ad = bb + ((u32)(wn * 64 + p * 16) + lrow) * 80u + (u32)ks * 32u + lkb16;
                ldsm4(bh[2 * p][0], bh[2 * p][1], bh[2 * p + 1][0], bh[2 * p + 1][1], ad);
                ldsm4(bl[2 * p][0], bl[2 * p][1], bl[2 * p + 1][0], bl[2 * p + 1][1],
                      ad + 10240u);
            }
#pragma unroll
            for (int mt = 0; mt < 2; mt++)
#pragma unroll
                for (int nt = 0; nt < 8; nt++) mma16816(d[mt][nt], ah[ks][mt], bh[nt]);
#pragma unroll
            for (int mt = 0; mt < 2; mt++)
#pragma unroll
                for (int nt = 0; nt < 8; nt++) mma16816(d[mt][nt], al[ks][mt], bh[nt]);
#pragma unroll
            for (int mt = 0; mt < 2; mt++)
#pragma unroll
                for (int nt = 0; nt < 8; nt++) mma16816(d[mt][nt], ah[ks][mt], bl[nt]);
        }
        __syncthreads();
    }

    // epilogue: bias + relu, f32 store
#pragma unroll
    for (int nt = 0; nt < 8; nt++) {
        int col = bn + wn * 64 + nt * 8 + (lane & 3) * 2;
        float b0 = b[col], b1 = b[col + 1];
#pragma unroll
        for (int mt = 0; mt < 2; mt++)
#pragma unroll
            for (int rp = 0; rp < 2; rp++) {
                int row = bm + wm * 32 + mt * 16 + (lane >> 2) + rp * 8;
                float2 o;
                o.x = fmaxf(d[mt][nt][2 * rp] + b0, 0.f);
                o.y = fmaxf(d[mt][nt][2 * rp + 1] + b1, 0.f);
                *reinterpret_cast<float2*>(&g_fc1[(size_t)row * 1024 + col]) = o;
            }
    }
}

// ============================================================================
// fc2: [2048,1024] x [10,1024]^T + b. Warp per row.
// ============================================================================
__global__ void __launch_bounds__(256) k_fc2(const float* __restrict__ w,
                                             const float* __restrict__ b,
                                             float* __restrict__ out) {
    int warp = threadIdx.x >> 5, lane = threadIdx.x & 31;
    int row = blockIdx.x * 8 + warp;
    const float* a = &g_fc1[row * 1024];
    float acc[10];
#pragma unroll
    for (int n = 0; n < 10; n++) acc[n] = 0.f;
    for (int k = lane; k < 1024; k += 32) {
        float av = a[k];
#pragma unroll
        for (int n = 0; n < 10; n++) acc[n] += av * w[n * 1024 + k];
    }
#pragma unroll
    for (int n = 0; n < 10; n++)
#pragma unroll
        for (int off = 16; off > 0; off >>= 1)
            acc[n] += __shfl_xor_sync(0xffffffffu, acc[n], off);
    if (lane == 0) {
#pragma unroll
        for (int n = 0; n < 10; n++) out[row * 10 + n] = acc[n] + b[n];
    }
}

// ============================================================================
extern "C" void kernel_launch(void* const* d_in, const int* in_sizes, int n_in,
                              void* d_out, int out_size) {
    const float* x       = (const float*)d_in[0];
    const float* conv1_w = (const float*)d_in[1];
    const float* trelu_t = (const float*)d_in[2];
    const float* conv2_w = (const float*)d_in[3];
    const float* conv2_b = (const float*)d_in[4];
    const float* fc1_w   = (const float*)d_in[5];
    const float* fc1_b   = (const float*)d_in[6];
    const float* fc2_w   = (const float*)d_in[7];
    const float* fc2_b   = (const float*)d_in[8];
    float* out = (float*)d_out;

    const int SMEM2 = 2 * 43008;
    cudaFuncSetAttribute(k_conv2, cudaFuncAttributeMaxDynamicSharedMemorySize, SMEM2);

    k_prep_w2b<<<(5 * 2 * 64 * 168 + 255) / 256, 256>>>(conv2_w);
    k_prep_fc1w<<<1024, 256>>>(fc1_w);
    k_conv1<<<1024, 392>>>(x, conv1_w, trelu_t);
    k_conv2<<<3136, 128, SMEM2>>>(conv2_b);
    k_fc1<<<dim3(16, 8), 256>>>(fc1_b);
    k_fc2<<<256, 256>>>(fc2_w, fc2_b, out);
}

// round 8
// speedup vs baseline: 2.1060x; 1.1128x over previous
#include <cuda_runtime.h>
#include <cuda_bf16.h>
#include <cstdint>

typedef unsigned long long ull;
typedef unsigned short u16;
typedef unsigned int u32;

// ---------------- device scratch (static, zero-initialized) ----------------
__device__ __align__(16) u16   g_s1h[2048 * 18 * 18 * 32];  // conv1 out NHWC bf16 hi, halo 2
__device__ __align__(16) u16   g_s1l[2048 * 18 * 18 * 32];  // conv1 out bf16 lo
__device__ __align__(16) u16   g_s2h[2048 * 3136];          // conv2 pooled out bf16 hi [b][q*64+co]
__device__ __align__(16) u16   g_s2l[2048 * 3136];          // conv2 pooled out bf16 lo
__device__ __align__(16) float g_fc1[2048 * 1024];          // fc1 out (f32)
__device__ __align__(16) u16   g_fc1wh[1024 * 3136];        // fc1 w bf16 hi, K reordered (q,co)
__device__ __align__(16) u16   g_fc1wl[1024 * 3136];        // fc1 w bf16 lo
__device__ __align__(16) u16   g_w2b[5 * 2 * 64 * 168];     // conv2 B [dy][plane][n=64][k pad 168]

// ---------------- f32x2 helpers ----------------
__device__ __forceinline__ ull ffma2(ull a, ull b, ull c) {
    ull d; asm("fma.rn.f32x2 %0, %1, %2, %3;" : "=l"(d) : "l"(a), "l"(b), "l"(c)); return d;
}
__device__ __forceinline__ ull dup2(float v) {
    ull d; asm("mov.b64 %0, {%1, %1};" : "=l"(d) : "f"(v)); return d;
}
__device__ __forceinline__ ull pk2(float lo, float hi) {
    ull d; asm("mov.b64 %0, {%1, %2};" : "=l"(d) : "f"(lo), "f"(hi)); return d;
}
__device__ __forceinline__ void upk2(ull v, float& lo, float& hi) {
    asm("mov.b64 {%0, %1}, %2;" : "=f"(lo), "=f"(hi) : "l"(v));
}

// ---------------- cp.async ----------------
__device__ __forceinline__ void cp16u(u32 saddr, const void* g) {
    asm volatile("cp.async.ca.shared.global [%0], [%1], 16;" :: "r"(saddr), "l"(g));
}
__device__ __forceinline__ void cp_commit() { asm volatile("cp.async.commit_group;"); }
__device__ __forceinline__ void cp_wait0()  { asm volatile("cp.async.wait_group 0;"); }
__device__ __forceinline__ void cp_wait1()  { asm volatile("cp.async.wait_group 1;"); }

// ---------------- mma.sync / ldmatrix (base sm_103 features) ----------------
__device__ __forceinline__ void ldsm4(u32& r0, u32& r1, u32& r2, u32& r3, u32 addr) {
    asm volatile("ldmatrix.sync.aligned.m8n8.x4.shared.b16 {%0,%1,%2,%3}, [%4];"
                 : "=r"(r0), "=r"(r1), "=r"(r2), "=r"(r3) : "r"(addr));
}
__device__ __forceinline__ void mma16816(float* d, const u32* a, const u32* b) {
    asm volatile("mma.sync.aligned.m16n8k16.row.col.f32.bf16.bf16.f32 "
                 "{%0,%1,%2,%3}, {%4,%5,%6,%7}, {%8,%9}, {%0,%1,%2,%3};"
                 : "+f"(d[0]), "+f"(d[1]), "+f"(d[2]), "+f"(d[3])
                 : "r"(a[0]), "r"(a[1]), "r"(a[2]), "r"(a[3]), "r"(b[0]), "r"(b[1]));
}

__device__ __forceinline__ void ins4(float& a, float& b, float& c, float& d, float v) {
    if (v > d) {
        d = v;
        if (d > c) { float t = c; c = d; d = t;
            if (c > b) { t = b; b = c; c = t;
                if (b > a) { t = a; a = b; b = t; }
            }
        }
    }
}
__device__ __forceinline__ u32 bf16pack2(float x, float y) {
    __nv_bfloat16 hx = __float2bfloat16(x), hy = __float2bfloat16(y);
    return (u32)reinterpret_cast<u16&>(hx) | ((u32)reinterpret_cast<u16&>(hy) << 16);
}

// ============================================================================
// prep: conv2 B images [dy][plane][n=64][k pad 168], k = dx*32+ci, bf16 hi/lo
// ============================================================================
__global__ void k_prep_w2b(const float* __restrict__ w2) {
    int i = blockIdx.x * blockDim.x + threadIdx.x;
    if (i >= 5 * 2 * 64 * 168) return;
    int dy = i / 21504, r = i % 21504;
    int plane = r / 10752, r2 = r % 10752;
    int co = r2 / 168, k = r2 % 168;
    float v = 0.f;
    if (k < 160) {
        int dx = k >> 5, ci = k & 31;
        v = w2[(co * 32 + ci) * 25 + dy * 5 + dx];
    }
    __nv_bfloat16 h = __float2bfloat16(v);
    if (plane == 0) {
        g_w2b[i] = reinterpret_cast<u16&>(h);
    } else {
        __nv_bfloat16 l2 = __float2bfloat16(v - __bfloat162float(h));
        g_w2b[i] = reinterpret_cast<u16&>(l2);
    }
}

// ============================================================================
// prep: fc1 weight K-permute (k = co*49+q -> j = q*64+co) + bf16 hi/lo split
// ============================================================================
__global__ void __launch_bounds__(256) k_prep_fc1w(const float* __restrict__ w) {
    __shared__ float row[3136];
    int n = blockIdx.x;
    for (int i = threadIdx.x; i < 3136; i += 256) row[i] = w[n * 3136 + i];
    __syncthreads();
    for (int i = threadIdx.x; i < 3136; i += 256) {
        int q = i >> 6, co = i & 63;
        float v = row[co * 49 + q];
        __nv_bfloat16 h = __float2bfloat16(v);
        __nv_bfloat16 l2 = __float2bfloat16(v - __bfloat162float(h));
        g_fc1wh[n * 3136 + i] = reinterpret_cast<u16&>(h);
        g_fc1wl[n * 3136 + i] = reinterpret_cast<u16&>(l2);
    }
}

// ============================================================================
// conv1 (1->32, 5x5, pad2) + top-4 mask + threshold ReLU + 2x2 maxpool
// output NHWC bf16 hi/lo with 2-pixel halo (halo stays zero)
// ============================================================================
__global__ void __launch_bounds__(392) k_conv1(const float* __restrict__ xin,
                                               const float* __restrict__ w1,
                                               const float* __restrict__ tt) {
    __shared__ float s_in[2][1024];
    __shared__ ull   s_w[800];
    __shared__ float s_t[32];

    int tid = threadIdx.x;
    int img0 = blockIdx.x * 2;

    for (int i = tid; i < 800; i += 392) { float v = w1[i]; s_w[i] = dup2(v); }
    if (tid < 32) s_t[tid] = tt[tid];
    for (int i = tid; i < 2048; i += 392) ((float*)s_in)[i] = 0.f;
    __syncthreads();
    for (int i = tid; i < 1568; i += 392) {
        int im = i / 784, p = i % 784, y = p / 28, xx = p % 28;
        s_in[im][(y + 2) * 32 + xx + 2] = xin[(img0 + im) * 784 + p];
    }
    __syncthreads();

    int im = tid / 196, t = tid % 196;
    int py = t / 14, px = t % 14;
    const float* base = &s_in[im][(2 * py) * 32 + 2 * px];

    float win[6][6];
#pragma unroll
    for (int r = 0; r < 6; r++)
#pragma unroll
        for (int c = 0; c < 6; c++) win[r][c] = base[r * 32 + c];
    ull pr[30];
#pragma unroll
    for (int dy = 0; dy < 5; dy++)
#pragma unroll
        for (int c = 0; c < 6; c++) pr[dy * 6 + c] = pk2(win[dy][c], win[dy + 1][c]);

    float a0t = -3.4e38f, b0t = -3.4e38f, c0t = -3.4e38f, d0t = -3.4e38f;
    float a1t = -3.4e38f, b1t = -3.4e38f, c1t = -3.4e38f, d1t = -3.4e38f;
    float a2t = -3.4e38f, b2t = -3.4e38f, c2t = -3.4e38f, d2t = -3.4e38f;
    float a3t = -3.4e38f, b3t = -3.4e38f, c3t = -3.4e38f, d3t = -3.4e38f;

    for (int c = 0; c < 32; c++) {
        const ull* wc = &s_w[c * 25];
        ull A0 = 0ull, A1 = 0ull;
#pragma unroll
        for (int dy = 0; dy < 5; dy++)
#pragma unroll
            for (int dx = 0; dx < 5; dx++) {
                ull wv = wc[dy * 5 + dx];
                A0 = ffma2(pr[dy * 6 + dx], wv, A0);
                A1 = ffma2(pr[dy * 6 + dx + 1], wv, A1);
            }
        float v00, v10, v01, v11;
        upk2(A0, v00, v10); upk2(A1, v01, v11);
        ins4(a0t, b0t, c0t, d0t, v00);
        ins4(a1t, b1t, c1t, d1t, v10);
        ins4(a2t, b2t, c2t, d2t, v01);
        ins4(a3t, b3t, c3t, d3t, v11);
    }
    float k0 = d0t, k1 = d1t, k2 = d2t, k3 = d3t;

    int img = img0 + im;
    __align__(16) u16 oh[32], ol[32];
    for (int c = 0; c < 32; c++) {
        const ull* wc = &s_w[c * 25];
        ull A0 = 0ull, A1 = 0ull;
#pragma unroll
        for (int dy = 0; dy < 5; dy++)
#pragma unroll
            for (int dx = 0; dx < 5; dx++) {
                ull wv = wc[dy * 5 + dx];
                A0 = ffma2(pr[dy * 6 + dx], wv, A0);
                A1 = ffma2(pr[dy * 6 + dx + 1], wv, A1);
            }
        float v00, v10, v01, v11;
        upk2(A0, v00, v10); upk2(A1, v01, v11);
        float tc = s_t[c];
        float r0 = (v00 >= k0) ? fmaxf(v00 - tc, 0.f) : 0.f;
        float r1 = (v10 >= k1) ? fmaxf(v10 - tc, 0.f) : 0.f;
        float r2 = (v01 >= k2) ? fmaxf(v01 - tc, 0.f) : 0.f;
        float r3 = (v11 >= k3) ? fmaxf(v11 - tc, 0.f) : 0.f;
        float v = fmaxf(fmaxf(r0, r1), fmaxf(r2, r3));
        __nv_bfloat16 h = __float2bfloat16(v);
        oh[c] = reinterpret_cast<u16&>(h);
        __nv_bfloat16 l2 = __float2bfloat16(v - __bfloat162float(h));
        ol[c] = reinterpret_cast<u16&>(l2);
    }
    size_t ob = (((size_t)img * 18 + (py + 2)) * 18 + (px + 2)) * 32;
#pragma unroll
    for (int c8 = 0; c8 < 4; c8++) {
        *reinterpret_cast<uint4*>(g_s1h + ob + c8 * 8) = *reinterpret_cast<uint4*>(&oh[c8 * 8]);
        *reinterpret_cast<uint4*>(g_s1l + ob + c8 * 8) = *reinterpret_cast<uint4*>(&ol[c8 * 8]);
    }
}

// ============================================================================
// conv2 via mma.sync (bf16 hi/lo x3): 5 accumulated GEMMs, K=160 per dy.
// CTA = 256 threads / 8 warps, M=256 rows; warp = m32 x n64.
// B smem double-buffered (shared across 8 warps -> half the B traffic of
// the 128-thr version); A fragments straight from gmem.
// Epilogue: shfl quad max-pool + bias + relu -> bf16 hi/lo g_s2h/g_s2l.
// ============================================================================
__global__ void __launch_bounds__(256) k_conv2(const float* __restrict__ b2) {
    extern __shared__ __align__(16) char sm2[];
    u32 sB = (u32)__cvta_generic_to_shared(sm2);   // 2 x 43008 B buffers

    const int tid = threadIdx.x;
    const int warp = tid >> 5, lane = tid & 31;

    u32 off[4];
#pragma unroll
    for (int i = 0; i < 4; i++) {
        int r = warp * 32 + ((i & 1) << 3) + ((i >> 1) << 4) + (lane >> 2);
        int m = blockIdx.x * 256 + r;
        int g = m >> 2, j = m & 3;
        int b = g / 49, q = g % 49;
        int qy = q / 7, qx = q % 7;
        int py = 2 * qy + (j >> 1), px = 2 * qx + (j & 1);
        off[i] = (u32)(((b * 18 + py) * 18 + px) * 32);
    }
    const u16* __restrict__ ph = g_s1h;
    const u16* __restrict__ pl = g_s1l;

    for (int i = tid; i < 2688; i += 256)
        cp16u(sB + (u32)i * 16u, (const char*)g_w2b + (size_t)i * 16);
    cp_commit();

    float d[2][8][4];
#pragma unroll
    for (int mt = 0; mt < 2; mt++)
#pragma unroll
        for (int nt = 0; nt < 8; nt++)
#pragma unroll
            for (int e = 0; e < 4; e++) d[mt][nt][e] = 0.f;

    const u32 kb2 = (u32)(lane & 3) * 2u;
    const u32 lrow = (u32)((lane & 7) + ((lane >> 4) << 3));
    const u32 lkb16 = (u32)(((lane >> 3) & 1) << 4);

    for (int dy = 0; dy < 5; dy++) {
        if (dy < 4) {
            u32 dst = sB + (u32)((dy + 1) & 1) * 43008u;
            const char* src = (const char*)g_w2b + (size_t)(dy + 1) * 43008u;
            for (int i = tid; i < 2688; i += 256)
                cp16u(dst + (u32)i * 16u, src + (size_t)i * 16);
            cp_commit();
            cp_wait1();
        } else {
            cp_wait0();
        }
        __syncthreads();

        const u32 dyoff = (u32)dy * (18 * 32);
        const u32 bb = sB + (u32)(dy & 1) * 43008u;

#pragma unroll
        for (int s = 0; s < 10; s++) {
            u32 ah[2][4], al[2][4];
#pragma unroll
            for (int mt = 0; mt < 2; mt++) {
                u32 i0 = off[mt * 2]     + dyoff + (u32)s * 16u + kb2;
                u32 i1 = off[mt * 2 + 1] + dyoff + (u32)s * 16u + kb2;
                ah[mt][0] = *reinterpret_cast<const u32*>(ph + i0);
                ah[mt][1] = *reinterpret_cast<const u32*>(ph + i1);
                ah[mt][2] = *reinterpret_cast<const u32*>(ph + i0 + 8);
                ah[mt][3] = *reinterpret_cast<const u32*>(ph + i1 + 8);
                al[mt][0] = *reinterpret_cast<const u32*>(pl + i0);
                al[mt][1] = *reinterpret_cast<const u32*>(pl + i1);
                al[mt][2] = *reinterpret_cast<const u32*>(pl + i0 + 8);
                al[mt][3] = *reinterpret_cast<const u32*>(pl + i1 + 8);
            }
            u32 bh[8][2], bl[8][2];
#pragma unroll
            for (int p = 0; p < 4; p++) {
                u32 ad = bb + ((u32)p * 16u + lrow) * 336u + (u32)s * 32u + lkb16;
                ldsm4(bh[2 * p][0], bh[2 * p][1], bh[2 * p + 1][0], bh[2 * p + 1][1], ad);
                ldsm4(bl[2 * p][0], bl[2 * p][1], bl[2 * p + 1][0], bl[2 * p + 1][1],
                      ad + 21504u);
            }
#pragma unroll
            for (int mt = 0; mt < 2; mt++)
#pragma unroll
                for (int nt = 0; nt < 8; nt++) mma16816(d[mt][nt], ah[mt], bh[nt]);
#pragma unroll
            for (int mt = 0; mt < 2; mt++)
#pragma unroll
                for (int nt = 0; nt < 8; nt++) mma16816(d[mt][nt], al[mt], bh[nt]);
#pragma unroll
            for (int mt = 0; mt < 2; mt++)
#pragma unroll
                for (int nt = 0; nt < 8; nt++) mma16816(d[mt][nt], ah[mt], bl[nt]);
        }
        __syncthreads();
    }

    // epilogue: quad max-pool + bias + relu -> bf16 hi/lo planes
    float bA[8], bB[8];
#pragma unroll
    for (int nt = 0; nt < 8; nt++) {
        int co = nt * 8 + 2 * (lane & 3);
        bA[nt] = b2[co]; bB[nt] = b2[co + 1];
    }
    bool act = ((lane & 12) == 0);
#pragma unroll
    for (int mt = 0; mt < 2; mt++)
#pragma unroll
        for (int rp = 0; rp < 2; rp++) {
            int G = blockIdx.x * 64 + warp * 8 + mt * 4 + rp * 2 + (lane >> 4);
            int b_ = G / 49, q_ = G % 49;
            size_t obase = (size_t)b_ * 3136 + q_ * 64;
#pragma unroll
            for (int nt = 0; nt < 8; nt++) {
                float v0 = d[mt][nt][2 * rp];
                float v1 = d[mt][nt][2 * rp + 1];
                v0 = fmaxf(v0, __shfl_xor_sync(0xffffffffu, v0, 4));
                v0 = fmaxf(v0, __shfl_xor_sync(0xffffffffu, v0, 8));
                v1 = fmaxf(v1, __shfl_xor_sync(0xffffffffu, v1, 4));
                v1 = fmaxf(v1, __shfl_xor_sync(0xffffffffu, v1, 8));
                if (act) {
                    float ox = fmaxf(v0 + bA[nt], 0.f);
                    float oy = fmaxf(v1 + bB[nt], 0.f);
                    float lx, ly;
                    __nv_bfloat16 hx = __float2bfloat16(ox), hy = __float2bfloat16(oy);
                    lx = ox - __bfloat162float(hx);
                    ly = oy - __bfloat162float(hy);
                    size_t idx = obase + nt * 8 + 2 * (lane & 3);
                    *reinterpret_cast<u32*>(g_s2h + idx) =
                        (u32)reinterpret_cast<u16&>(hx) | ((u32)reinterpret_cast<u16&>(hy) << 16);
                    *reinterpret_cast<u32*>(g_s2l + idx) = bf16pack2(lx, ly);
                }
            }
        }
}

// ============================================================================
// fc1 via mma.sync (bf16 hi/lo x3): M=2048, N=1024, K=3136.
// CTA 256 thr / 8 warps = M128 x N128 tile; warp = m32 x n64.
// BOTH A and B staged in smem via coalesced cp.async (80B padded rows,
// conflict-free ldmatrix), double-buffered. Epilogue: bias+relu f32.
// smem: A [2][2][128][40] @0 (40960B), B same @40960. Total 81920B dynamic.
// ============================================================================
__global__ void __launch_bounds__(256) k_fc1(const float* __restrict__ b) {
    extern __shared__ __align__(16) char smf[];
    const u32 sbase = (u32)__cvta_generic_to_shared(smf);

    const int tid = threadIdx.x;
    const int warp = tid >> 5, lane = tid & 31;
    const int wm = warp >> 1, wn = warp & 1;
    const int bm = blockIdx.x * 128, bn = blockIdx.y * 128;

    const u32 lrow = (u32)((lane & 7) + ((lane >> 4) << 3));
    const u32 lkb16 = (u32)(((lane >> 3) & 1) << 4);
    const u32 arow16 = (u32)(lane & 15);
    const u32 acb16 = (u32)((lane >> 4) << 4);

    // chunk loader: A (1024 cp16) + B (1024 cp16)
    auto load_chunk = [&](int buf, int k0) {
        u32 abase = sbase + (u32)buf * 20480u;
        u32 bbase = sbase + 40960u + (u32)buf * 20480u;
        for (int i = tid; i < 2048; i += 256) {
            int sel = i >> 10;
            int r = i & 1023;
            int plane = r >> 9, rr = r & 511;
            int row = rr >> 2, qh = rr & 3;
            const u16* src;
            u32 dst;
            if (sel == 0) {
                src = (plane ? g_s2l : g_s2h) + (size_t)(bm + row) * 3136 + k0 + qh * 8;
                dst = abase;
            } else {
                src = (plane ? g_fc1wl : g_fc1wh) + (size_t)(bn + row) * 3136 + k0 + qh * 8;
                dst = bbase;
            }
            cp16u(dst + (u32)plane * 10240u + (u32)row * 80u + (u32)qh * 16u, src);
        }
    };

    load_chunk(0, 0);
    cp_commit();

    float d[2][8][4];
#pragma unroll
    for (int mt = 0; mt < 2; mt++)
#pragma unroll
        for (int nt = 0; nt < 8; nt++)
#pragma unroll
            for (int e = 0; e < 4; e++) d[mt][nt][e] = 0.f;

    for (int kt = 0; kt < 98; kt++) {
        if (kt < 97) {
            load_chunk((kt + 1) & 1, (kt + 1) * 32);
            cp_commit();
            cp_wait1();
        } else {
            cp_wait0();
        }
        __syncthreads();

        const u32 abuf = sbase + (u32)(kt & 1) * 20480u;
        const u32 bbuf = sbase + 40960u + (u32)(kt & 1) * 20480u;

#pragma unroll
        for (int ks = 0; ks < 2; ks++) {
            u32 ah[2][4], al[2][4];
#pragma unroll
            for (int mt = 0; mt < 2; mt++) {
                u32 ar = abuf + ((u32)(wm * 32 + mt * 16) + arow16) * 80u
                       + (u32)ks * 32u + acb16;
                ldsm4(ah[mt][0], ah[mt][1], ah[mt][2], ah[mt][3], ar);
                ldsm4(al[mt][0], al[mt][1], al[mt][2], al[mt][3], ar + 10240u);
            }
            u32 bh[8][2], bl[8][2];
#pragma unroll
            for (int p = 0; p < 4; p++) {
                u32 ad = bbuf + ((u32)(wn * 64 + p * 16) + lrow) * 80u
                       + (u32)ks * 32u + lkb16;
                ldsm4(bh[2 * p][0], bh[2 * p][1], bh[2 * p + 1][0], bh[2 * p + 1][1], ad);
                ldsm4(bl[2 * p][0], bl[2 * p][1], bl[2 * p + 1][0], bl[2 * p + 1][1],
                      ad + 10240u);
            }
#pragma unroll
            for (int mt = 0; mt < 2; mt++)
#pragma unroll
                for (int nt = 0; nt < 8; nt++) mma16816(d[mt][nt], ah[mt], bh[nt]);
#pragma unroll
            for (int mt = 0; mt < 2; mt++)
#pragma unroll
                for (int nt = 0; nt < 8; nt++) mma16816(d[mt][nt], al[mt], bh[nt]);
#pragma unroll
            for (int mt = 0; mt < 2; mt++)
#pragma unroll
                for (int nt = 0; nt < 8; nt++) mma16816(d[mt][nt], ah[mt], bl[nt]);
        }
        __syncthreads();
    }

    // epilogue: bias + relu, f32 store
#pragma unroll
    for (int nt = 0; nt < 8; nt++) {
        int col = bn + wn * 64 + nt * 8 + (lane & 3) * 2;
        float b0 = b[col], b1 = b[col + 1];
#pragma unroll
        for (int mt = 0; mt < 2; mt++)
#pragma unroll
            for (int rp = 0; rp < 2; rp++) {
                int row = bm + wm * 32 + mt * 16 + (lane >> 2) + rp * 8;
                float2 o;
                o.x = fmaxf(d[mt][nt][2 * rp] + b0, 0.f);
                o.y = fmaxf(d[mt][nt][2 * rp + 1] + b1, 0.f);
                *reinterpret_cast<float2*>(&g_fc1[(size_t)row * 1024 + col]) = o;
            }
    }
}

// ============================================================================
// fc2: [2048,1024] x [10,1024]^T + b. Warp per row.
// ============================================================================
__global__ void __launch_bounds__(256) k_fc2(const float* __restrict__ w,
                                             const float* __restrict__ b,
                                             float* __restrict__ out) {
    int warp = threadIdx.x >> 5, lane = threadIdx.x & 31;
    int row = blockIdx.x * 8 + warp;
    const float* a = &g_fc1[row * 1024];
    float acc[10];
#pragma unroll
    for (int n = 0; n < 10; n++) acc[n] = 0.f;
    for (int k = lane; k < 1024; k += 32) {
        float av = a[k];
#pragma unroll
        for (int n = 0; n < 10; n++) acc[n] += av * w[n * 1024 + k];
    }
#pragma unroll
    for (int n = 0; n < 10; n++)
#pragma unroll
        for (int off = 16; off > 0; off >>= 1)
            acc[n] += __shfl_xor_sync(0xffffffffu, acc[n], off);
    if (lane == 0) {
#pragma unroll
        for (int n = 0; n < 10; n++) out[row * 10 + n] = acc[n] + b[n];
    }
}

// ============================================================================
extern "C" void kernel_launch(void* const* d_in, const int* in_sizes, int n_in,
                              void* d_out, int out_size) {
    const float* x       = (const float*)d_in[0];
    const float* conv1_w = (const float*)d_in[1];
    const float* trelu_t = (const float*)d_in[2];
    const float* conv2_w = (const float*)d_in[3];
    const float* conv2_b = (const float*)d_in[4];
    const float* fc1_w   = (const float*)d_in[5];
    const float* fc1_b   = (const float*)d_in[6];
    const float* fc2_w   = (const float*)d_in[7];
    const float* fc2_b   = (const float*)d_in[8];
    float* out = (float*)d_out;

    const int SMEM2 = 2 * 43008;
    const int SMEMF = 2 * 40960;
    cudaFuncSetAttribute(k_conv2, cudaFuncAttributeMaxDynamicSharedMemorySize, SMEM2);
    cudaFuncSetAttribute(k_fc1, cudaFuncAttributeMaxDynamicSharedMemorySize, SMEMF);

    k_prep_w2b<<<(5 * 2 * 64 * 168 + 255) / 256, 256>>>(conv2_w);
    k_prep_fc1w<<<1024, 256>>>(fc1_w);
    k_conv1<<<1024, 392>>>(x, conv1_w, trelu_t);
    k_conv2<<<1568, 256, SMEM2>>>(conv2_b);
    k_fc1<<<dim3(16, 8), 256, SMEMF>>>(fc1_b);
    k_fc2<<<256, 256>>>(fc2_w, fc2_b, out);
}

// round 9
// speedup vs baseline: 2.2606x; 1.0734x over previous
#include <cuda_runtime.h>
#include <cuda_bf16.h>
#include <cstdint>

typedef unsigned long long ull;
typedef unsigned short u16;
typedef unsigned int u32;

// ---------------- device scratch (static, zero-initialized) ----------------
// conv1 out, packed-interleave layout: per (b, padded_y) row of 18 pixels,
// 36 k-groups of 16 elems; each group = 4 c-blocks of 8 u16:
// {hi[2c],hi[2c+1],lo[2c],lo[2c+1],hi[2c+8],hi[2c+9],lo[2c+8],lo[2c+9]}
__device__ __align__(16) u16   g_s1p[2048 * 18 * 18 * 2 * 32]; // halo stays 0
__device__ __align__(16) u16   g_s2h[2048 * 3136];          // conv2 out bf16 hi [b][q*64+co]
__device__ __align__(16) u16   g_s2l[2048 * 3136];          // conv2 out bf16 lo
__device__ __align__(16) float g_fc1[2048 * 1024];          // fc1 out (f32)
__device__ __align__(16) u16   g_fc1wh[1024 * 3136];        // fc1 w bf16 hi, K (q,co)
__device__ __align__(16) u16   g_fc1wl[1024 * 3136];        // fc1 w bf16 lo
__device__ __align__(16) u16   g_w2b[5 * 2 * 64 * 168];     // conv2 B [dy][plane][n][k pad 168]

// ---------------- f32x2 helpers ----------------
__device__ __forceinline__ ull ffma2(ull a, ull b, ull c) {
    ull d; asm("fma.rn.f32x2 %0, %1, %2, %3;" : "=l"(d) : "l"(a), "l"(b), "l"(c)); return d;
}
__device__ __forceinline__ ull dup2(float v) {
    ull d; asm("mov.b64 %0, {%1, %1};" : "=l"(d) : "f"(v)); return d;
}
__device__ __forceinline__ ull pk2(float lo, float hi) {
    ull d; asm("mov.b64 %0, {%1, %2};" : "=l"(d) : "f"(lo), "f"(hi)); return d;
}
__device__ __forceinline__ void upk2(ull v, float& lo, float& hi) {
    asm("mov.b64 {%0, %1}, %2;" : "=f"(lo), "=f"(hi) : "l"(v));
}

// ---------------- cp.async ----------------
__device__ __forceinline__ void cp16u(u32 saddr, const void* g) {
    asm volatile("cp.async.ca.shared.global [%0], [%1], 16;" :: "r"(saddr), "l"(g));
}
__device__ __forceinline__ void cp_commit() { asm volatile("cp.async.commit_group;"); }
__device__ __forceinline__ void cp_wait0()  { asm volatile("cp.async.wait_group 0;"); }
__device__ __forceinline__ void cp_wait1()  { asm volatile("cp.async.wait_group 1;"); }

// ---------------- mma.sync / ldmatrix ----------------
__device__ __forceinline__ void ldsm4(u32& r0, u32& r1, u32& r2, u32& r3, u32 addr) {
    asm volatile("ldmatrix.sync.aligned.m8n8.x4.shared.b16 {%0,%1,%2,%3}, [%4];"
                 : "=r"(r0), "=r"(r1), "=r"(r2), "=r"(r3) : "r"(addr));
}
__device__ __forceinline__ void mma16816(float* d, const u32* a, const u32* b) {
    asm volatile("mma.sync.aligned.m16n8k16.row.col.f32.bf16.bf16.f32 "
                 "{%0,%1,%2,%3}, {%4,%5,%6,%7}, {%8,%9}, {%0,%1,%2,%3};"
                 : "+f"(d[0]), "+f"(d[1]), "+f"(d[2]), "+f"(d[3])
                 : "r"(a[0]), "r"(a[1]), "r"(a[2]), "r"(a[3]), "r"(b[0]), "r"(b[1]));
}

__device__ __forceinline__ void ins4(float& a, float& b, float& c, float& d, float v) {
    if (v > d) {
        d = v;
        if (d > c) { float t = c; c = d; d = t;
            if (c > b) { t = b; b = c; c = t;
                if (b > a) { t = a; a = b; b = t; }
            }
        }
    }
}
__device__ __forceinline__ u32 bf16pack2(float x, float y) {
    __nv_bfloat16 hx = __float2bfloat16(x), hy = __float2bfloat16(y);
    return (u32)reinterpret_cast<u16&>(hx) | ((u32)reinterpret_cast<u16&>(hy) << 16);
}

// ============================================================================
// prep: conv2 B images [dy][plane][n=64][k pad 168], k = dx*32+ci, bf16 hi/lo
// ============================================================================
__global__ void k_prep_w2b(const float* __restrict__ w2) {
    int i = blockIdx.x * blockDim.x + threadIdx.x;
    if (i >= 5 * 2 * 64 * 168) return;
    int dy = i / 21504, r = i % 21504;
    int plane = r / 10752, r2 = r % 10752;
    int co = r2 / 168, k = r2 % 168;
    float v = 0.f;
    if (k < 160) {
        int dx = k >> 5, ci = k & 31;
        v = w2[(co * 32 + ci) * 25 + dy * 5 + dx];
    }
    __nv_bfloat16 h = __float2bfloat16(v);
    if (plane == 0) {
        g_w2b[i] = reinterpret_cast<u16&>(h);
    } else {
        __nv_bfloat16 l2 = __float2bfloat16(v - __bfloat162float(h));
        g_w2b[i] = reinterpret_cast<u16&>(l2);
    }
}

// ============================================================================
// prep: fc1 weight K-permute (k = co*49+q -> j = q*64+co) + bf16 hi/lo split
// ============================================================================
__global__ void __launch_bounds__(256) k_prep_fc1w(const float* __restrict__ w) {
    __shared__ float row[3136];
    int n = blockIdx.x;
    for (int i = threadIdx.x; i < 3136; i += 256) row[i] = w[n * 3136 + i];
    __syncthreads();
    for (int i = threadIdx.x; i < 3136; i += 256) {
        int q = i >> 6, co = i & 63;
        float v = row[co * 49 + q];
        __nv_bfloat16 h = __float2bfloat16(v);
        __nv_bfloat16 l2 = __float2bfloat16(v - __bfloat162float(h));
        g_fc1wh[n * 3136 + i] = reinterpret_cast<u16&>(h);
        g_fc1wl[n * 3136 + i] = reinterpret_cast<u16&>(l2);
    }
}

// ============================================================================
// conv1 (1->32, 5x5, pad2) + top-4 mask + threshold ReLU + 2x2 maxpool
// output: packed-interleave hi/lo layout (g_s1p), 2-pixel halo stays zero
// ============================================================================
__global__ void __launch_bounds__(392) k_conv1(const float* __restrict__ xin,
                                               const float* __restrict__ w1,
                                               const float* __restrict__ tt) {
    __shared__ float s_in[2][1024];
    __shared__ ull   s_w[800];
    __shared__ float s_t[32];

    int tid = threadIdx.x;
    int img0 = blockIdx.x * 2;

    for (int i = tid; i < 800; i += 392) { float v = w1[i]; s_w[i] = dup2(v); }
    if (tid < 32) s_t[tid] = tt[tid];
    for (int i = tid; i < 2048; i += 392) ((float*)s_in)[i] = 0.f;
    __syncthreads();
    for (int i = tid; i < 1568; i += 392) {
        int im = i / 784, p = i % 784, y = p / 28, xx = p % 28;
        s_in[im][(y + 2) * 32 + xx + 2] = xin[(img0 + im) * 784 + p];
    }
    __syncthreads();

    int im = tid / 196, t = tid % 196;
    int py = t / 14, px = t % 14;
    const float* base = &s_in[im][(2 * py) * 32 + 2 * px];

    float win[6][6];
#pragma unroll
    for (int r = 0; r < 6; r++)
#pragma unroll
        for (int c = 0; c < 6; c++) win[r][c] = base[r * 32 + c];
    ull pr[30];
#pragma unroll
    for (int dy = 0; dy < 5; dy++)
#pragma unroll
        for (int c = 0; c < 6; c++) pr[dy * 6 + c] = pk2(win[dy][c], win[dy + 1][c]);

    float a0t = -3.4e38f, b0t = -3.4e38f, c0t = -3.4e38f, d0t = -3.4e38f;
    float a1t = -3.4e38f, b1t = -3.4e38f, c1t = -3.4e38f, d1t = -3.4e38f;
    float a2t = -3.4e38f, b2t = -3.4e38f, c2t = -3.4e38f, d2t = -3.4e38f;
    float a3t = -3.4e38f, b3t = -3.4e38f, c3t = -3.4e38f, d3t = -3.4e38f;

    for (int c = 0; c < 32; c++) {
        const ull* wc = &s_w[c * 25];
        ull A0 = 0ull, A1 = 0ull;
#pragma unroll
        for (int dy = 0; dy < 5; dy++)
#pragma unroll
            for (int dx = 0; dx < 5; dx++) {
                ull wv = wc[dy * 5 + dx];
                A0 = ffma2(pr[dy * 6 + dx], wv, A0);
                A1 = ffma2(pr[dy * 6 + dx + 1], wv, A1);
            }
        float v00, v10, v01, v11;
        upk2(A0, v00, v10); upk2(A1, v01, v11);
        ins4(a0t, b0t, c0t, d0t, v00);
        ins4(a1t, b1t, c1t, d1t, v10);
        ins4(a2t, b2t, c2t, d2t, v01);
        ins4(a3t, b3t, c3t, d3t, v11);
    }
    float k0 = d0t, k1 = d1t, k2 = d2t, k3 = d3t;

    int img = img0 + im;
    u16 oh[32], ol[32];
    for (int c = 0; c < 32; c++) {
        const ull* wc = &s_w[c * 25];
        ull A0 = 0ull, A1 = 0ull;
#pragma unroll
        for (int dy = 0; dy < 5; dy++)
#pragma unroll
            for (int dx = 0; dx < 5; dx++) {
                ull wv = wc[dy * 5 + dx];
                A0 = ffma2(pr[dy * 6 + dx], wv, A0);
                A1 = ffma2(pr[dy * 6 + dx + 1], wv, A1);
            }
        float v00, v10, v01, v11;
        upk2(A0, v00, v10); upk2(A1, v01, v11);
        float tc = s_t[c];
        float r0 = (v00 >= k0) ? fmaxf(v00 - tc, 0.f) : 0.f;
        float r1 = (v10 >= k1) ? fmaxf(v10 - tc, 0.f) : 0.f;
        float r2 = (v01 >= k2) ? fmaxf(v01 - tc, 0.f) : 0.f;
        float r3 = (v11 >= k3) ? fmaxf(v11 - tc, 0.f) : 0.f;
        float v = fmaxf(fmaxf(r0, r1), fmaxf(r2, r3));
        __nv_bfloat16 h = __float2bfloat16(v);
        oh[c] = reinterpret_cast<u16&>(h);
        __nv_bfloat16 l2 = __float2bfloat16(v - __bfloat162float(h));
        ol[c] = reinterpret_cast<u16&>(l2);
    }
    // pack into interleaved layout: 2 groups x 4 c-blocks of 8 u16
    size_t gb = ((((size_t)img * 18 + (py + 2)) * 18 + (px + 2)) * 2) * 32;
#pragma unroll
    for (int g = 0; g < 2; g++) {
#pragma unroll
        for (int c = 0; c < 4; c++) {
            __align__(16) u16 buf[8];
            buf[0] = oh[g * 16 + 2 * c];     buf[1] = oh[g * 16 + 2 * c + 1];
            buf[2] = ol[g * 16 + 2 * c];     buf[3] = ol[g * 16 + 2 * c + 1];
            buf[4] = oh[g * 16 + 2 * c + 8]; buf[5] = oh[g * 16 + 2 * c + 9];
            buf[6] = ol[g * 16 + 2 * c + 8]; buf[7] = ol[g * 16 + 2 * c + 9];
            *reinterpret_cast<uint4*>(g_s1p + gb + g * 32 + c * 8) =
                *reinterpret_cast<uint4*>(buf);
        }
    }
}

// ============================================================================
// conv2 via mma.sync (bf16 hi/lo x3): 5 accumulated GEMMs, K=160 per dy.
// CTA = 256 threads / 8 warps, M=256 rows; warp = m32 x n64, 2 CTAs/SM.
// A fragments: one LDG.128 per (row, k-step) from packed-interleave layout.
// B smem double-buffered. Epilogue: shfl quad max-pool + bias + relu.
// ============================================================================
__global__ void __launch_bounds__(256, 2) k_conv2(const float* __restrict__ b2) {
    extern __shared__ __align__(16) char sm2[];
    u32 sB = (u32)__cvta_generic_to_shared(sm2);   // 2 x 43008 B buffers

    const int tid = threadIdx.x;
    const int warp = tid >> 5, lane = tid & 31;

    // group-base (u16 index) per A row, incl. this lane's c-block offset
    u32 grpb[4];
#pragma unroll
    for (int i = 0; i < 4; i++) {
        int r = warp * 32 + ((i & 1) << 3) + ((i >> 1) << 4) + (lane >> 2);
        int m = blockIdx.x * 256 + r;
        int g = m >> 2, j = m & 3;
        int b = g / 49, q = g % 49;
        int qy = q / 7, qx = q % 7;
        int py = 2 * qy + (j >> 1), px = 2 * qx + (j & 1);
        grpb[i] = (u32)(((b * 18 + py) * 18 + px) * 2) * 32u + (u32)(lane & 3) * 8u;
    }
    const u16* __restrict__ pp = g_s1p;

    for (int i = tid; i < 2688; i += 256)
        cp16u(sB + (u32)i * 16u, (const char*)g_w2b + (size_t)i * 16);
    cp_commit();

    float d[2][8][4];
#pragma unroll
    for (int mt = 0; mt < 2; mt++)
#pragma unroll
        for (int nt = 0; nt < 8; nt++)
#pragma unroll
            for (int e = 0; e < 4; e++) d[mt][nt][e] = 0.f;

    const u32 lrow = (u32)((lane & 7) + ((lane >> 4) << 3));
    const u32 lkb16 = (u32)(((lane >> 3) & 1) << 4);

    for (int dy = 0; dy < 5; dy++) {
        if (dy < 4) {
            u32 dst = sB + (u32)((dy + 1) & 1) * 43008u;
            const char* src = (const char*)g_w2b + (size_t)(dy + 1) * 43008u;
            for (int i = tid; i < 2688; i += 256)
                cp16u(dst + (u32)i * 16u, src + (size_t)i * 16);
            cp_commit();
            cp_wait1();
        } else {
            cp_wait0();
        }
        __syncthreads();

        const u32 dygrp = (u32)dy * 36u;          // group rows per dy
        const u32 bb = sB + (u32)(dy & 1) * 43008u;

#pragma unroll
        for (int s = 0; s < 10; s++) {
            const u32 goff = (dygrp + (u32)s) * 32u;
            u32 ah[2][4], al[2][4];
#pragma unroll
            for (int mt = 0; mt < 2; mt++) {
                uint4 q0 = *reinterpret_cast<const uint4*>(pp + grpb[mt * 2] + goff);
                uint4 q1 = *reinterpret_cast<const uint4*>(pp + grpb[mt * 2 + 1] + goff);
                ah[mt][0] = q0.x; al[mt][0] = q0.y; ah[mt][2] = q0.z; al[mt][2] = q0.w;
                ah[mt][1] = q1.x; al[mt][1] = q1.y; ah[mt][3] = q1.z; al[mt][3] = q1.w;
            }
            u32 bh[8][2], bl[8][2];
#pragma unroll
            for (int p = 0; p < 4; p++) {
                u32 ad = bb + ((u32)p * 16u + lrow) * 336u + (u32)s * 32u + lkb16;
                ldsm4(bh[2 * p][0], bh[2 * p][1], bh[2 * p + 1][0], bh[2 * p + 1][1], ad);
                ldsm4(bl[2 * p][0], bl[2 * p][1], bl[2 * p + 1][0], bl[2 * p + 1][1],
                      ad + 21504u);
            }
#pragma unroll
            for (int mt = 0; mt < 2; mt++)
#pragma unroll
                for (int nt = 0; nt < 8; nt++) mma16816(d[mt][nt], ah[mt], bh[nt]);
#pragma unroll
            for (int mt = 0; mt < 2; mt++)
#pragma unroll
                for (int nt = 0; nt < 8; nt++) mma16816(d[mt][nt], al[mt], bh[nt]);
#pragma unroll
            for (int mt = 0; mt < 2; mt++)
#pragma unroll
                for (int nt = 0; nt < 8; nt++) mma16816(d[mt][nt], ah[mt], bl[nt]);
        }
        __syncthreads();
    }

    // epilogue: quad max-pool + bias + relu -> bf16 hi/lo planes
    float bA[8], bB[8];
#pragma unroll
    for (int nt = 0; nt < 8; nt++) {
        int co = nt * 8 + 2 * (lane & 3);
        bA[nt] = b2[co]; bB[nt] = b2[co + 1];
    }
    bool act = ((lane & 12) == 0);
#pragma unroll
    for (int mt = 0; mt < 2; mt++)
#pragma unroll
        for (int rp = 0; rp < 2; rp++) {
            int G = blockIdx.x * 64 + warp * 8 + mt * 4 + rp * 2 + (lane >> 4);
            int b_ = G / 49, q_ = G % 49;
            size_t obase = (size_t)b_ * 3136 + q_ * 64;
#pragma unroll
            for (int nt = 0; nt < 8; nt++) {
                float v0 = d[mt][nt][2 * rp];
                float v1 = d[mt][nt][2 * rp + 1];
                v0 = fmaxf(v0, __shfl_xor_sync(0xffffffffu, v0, 4));
                v0 = fmaxf(v0, __shfl_xor_sync(0xffffffffu, v0, 8));
                v1 = fmaxf(v1, __shfl_xor_sync(0xffffffffu, v1, 4));
                v1 = fmaxf(v1, __shfl_xor_sync(0xffffffffu, v1, 8));
                if (act) {
                    float ox = fmaxf(v0 + bA[nt], 0.f);
                    float oy = fmaxf(v1 + bB[nt], 0.f);
                    __nv_bfloat16 hx = __float2bfloat16(ox), hy = __float2bfloat16(oy);
                    float lx = ox - __bfloat162float(hx);
                    float ly = oy - __bfloat162float(hy);
                    size_t idx = obase + nt * 8 + 2 * (lane & 3);
                    *reinterpret_cast<u32*>(g_s2h + idx) =
                        (u32)reinterpret_cast<u16&>(hx) | ((u32)reinterpret_cast<u16&>(hy) << 16);
                    *reinterpret_cast<u32*>(g_s2l + idx) = bf16pack2(lx, ly);
                }
            }
        }
}

// ============================================================================
// fc1 via mma.sync (bf16 hi/lo x3): M=2048, N=1024, K=3136.
// CTA 256 thr / 8 warps = M128 x N128; A and B both smem-staged (cp.async,
// 80B padded rows, conflict-free ldmatrix), double-buffered.
// ============================================================================
__global__ void __launch_bounds__(256) k_fc1(const float* __restrict__ b) {
    extern __shared__ __align__(16) char smf[];
    const u32 sbase = (u32)__cvta_generic_to_shared(smf);

    const int tid = threadIdx.x;
    const int warp = tid >> 5, lane = tid & 31;
    const int wm = warp >> 1, wn = warp & 1;
    const int bm = blockIdx.x * 128, bn = blockIdx.y * 128;

    const u32 lrow = (u32)((lane & 7) + ((lane >> 4) << 3));
    const u32 lkb16 = (u32)(((lane >> 3) & 1) << 4);
    const u32 arow16 = (u32)(lane & 15);
    const u32 acb16 = (u32)((lane >> 4) << 4);

    auto load_chunk = [&](int buf, int k0) {
        u32 abase = sbase + (u32)buf * 20480u;
        u32 bbase = sbase + 40960u + (u32)buf * 20480u;
        for (int i = tid; i < 2048; i += 256) {
            int sel = i >> 10;
            int r = i & 1023;
            int plane = r >> 9, rr = r & 511;
            int row = rr >> 2, qh = rr & 3;
            const u16* src;
            u32 dst;
            if (sel == 0) {
                src = (plane ? g_s2l : g_s2h) + (size_t)(bm + row) * 3136 + k0 + qh * 8;
                dst = abase;
            } else {
                src = (plane ? g_fc1wl : g_fc1wh) + (size_t)(bn + row) * 3136 + k0 + qh * 8;
                dst = bbase;
            }
            cp16u(dst + (u32)plane * 10240u + (u32)row * 80u + (u32)qh * 16u, src);
        }
    };

    load_chunk(0, 0);
    cp_commit();

    float d[2][8][4];
#pragma unroll
    for (int mt = 0; mt < 2; mt++)
#pragma unroll
        for (int nt = 0; nt < 8; nt++)
#pragma unroll
            for (int e = 0; e < 4; e++) d[mt][nt][e] = 0.f;

    for (int kt = 0; kt < 98; kt++) {
        if (kt < 97) {
            load_chunk((kt + 1) & 1, (kt + 1) * 32);
            cp_commit();
            cp_wait1();
        } else {
            cp_wait0();
        }
        __syncthreads();

        const u32 abuf = sbase + (u32)(kt & 1) * 20480u;
        const u32 bbuf = sbase + 40960u + (u32)(kt & 1) * 20480u;

#pragma unroll
        for (int ks = 0; ks < 2; ks++) {
            u32 ah[2][4], al[2][4];
#pragma unroll
            for (int mt = 0; mt < 2; mt++) {
                u32 ar = abuf + ((u32)(wm * 32 + mt * 16) + arow16) * 80u
                       + (u32)ks * 32u + acb16;
                ldsm4(ah[mt][0], ah[mt][1], ah[mt][2], ah[mt][3], ar);
                ldsm4(al[mt][0], al[mt][1], al[mt][2], al[mt][3], ar + 10240u);
            }
            u32 bh[8][2], bl[8][2];
#pragma unroll
            for (int p = 0; p < 4; p++) {
                u32 ad = bbuf + ((u32)(wn * 64 + p * 16) + lrow) * 80u
                       + (u32)ks * 32u + lkb16;
                ldsm4(bh[2 * p][0], bh[2 * p][1], bh[2 * p + 1][0], bh[2 * p + 1][1], ad);
                ldsm4(bl[2 * p][0], bl[2 * p][1], bl[2 * p + 1][0], bl[2 * p + 1][1],
                      ad + 10240u);
            }
#pragma unroll
            for (int mt = 0; mt < 2; mt++)
#pragma unroll
                for (int nt = 0; nt < 8; nt++) mma16816(d[mt][nt], ah[mt], bh[nt]);
#pragma unroll
            for (int mt = 0; mt < 2; mt++)
#pragma unroll
                for (int nt = 0; nt < 8; nt++) mma16816(d[mt][nt], al[mt], bh[nt]);
#pragma unroll
            for (int mt = 0; mt < 2; mt++)
#pragma unroll
                for (int nt = 0; nt < 8; nt++) mma16816(d[mt][nt], ah[mt], bl[nt]);
        }
        __syncthreads();
    }

#pragma unroll
    for (int nt = 0; nt < 8; nt++) {
        int col = bn + wn * 64 + nt * 8 + (lane & 3) * 2;
        float b0 = b[col], b1 = b[col + 1];
#pragma unroll
        for (int mt = 0; mt < 2; mt++)
#pragma unroll
            for (int rp = 0; rp < 2; rp++) {
                int row = bm + wm * 32 + mt * 16 + (lane >> 2) + rp * 8;
                float2 o;
                o.x = fmaxf(d[mt][nt][2 * rp] + b0, 0.f);
                o.y = fmaxf(d[mt][nt][2 * rp + 1] + b1, 0.f);
                *reinterpret_cast<float2*>(&g_fc1[(size_t)row * 1024 + col]) = o;
            }
    }
}

// ============================================================================
// fc2: [2048,1024] x [10,1024]^T + b. Warp per row.
// ============================================================================
__global__ void __launch_bounds__(256) k_fc2(const float* __restrict__ w,
                                             const float* __restrict__ b,
                                             float* __restrict__ out) {
    int warp = threadIdx.x >> 5, lane = threadIdx.x & 31;
    int row = blockIdx.x * 8 + warp;
    const float* a = &g_fc1[row * 1024];
    float acc[10];
#pragma unroll
    for (int n = 0; n < 10; n++) acc[n] = 0.f;
    for (int k = lane; k < 1024; k += 32) {
        float av = a[k];
#pragma unroll
        for (int n = 0; n < 10; n++) acc[n] += av * w[n * 1024 + k];
    }
#pragma unroll
    for (int n = 0; n < 10; n++)
#pragma unroll
        for (int off = 16; off > 0; off >>= 1)
            acc[n] += __shfl_xor_sync(0xffffffffu, acc[n], off);
    if (lane == 0) {
#pragma unroll
        for (int n = 0; n < 10; n++) out[row * 10 + n] = acc[n] + b[n];
    }
}

// ============================================================================
extern "C" void kernel_launch(void* const* d_in, const int* in_sizes, int n_in,
                              void* d_out, int out_size) {
    const float* x       = (const float*)d_in[0];
    const float* conv1_w = (const float*)d_in[1];
    const float* trelu_t = (const float*)d_in[2];
    const float* conv2_w = (const float*)d_in[3];
    const float* conv2_b = (const float*)d_in[4];
    const float* fc1_w   = (const float*)d_in[5];
    const float* fc1_b   = (const float*)d_in[6];
    const float* fc2_w   = (const float*)d_in[7];
    const float* fc2_b   = (const float*)d_in[8];
    float* out = (float*)d_out;

    const int SMEM2 = 2 * 43008;
    const int SMEMF = 2 * 40960;
    cudaFuncSetAttribute(k_conv2, cudaFuncAttributeMaxDynamicSharedMemorySize, SMEM2);
    cudaFuncSetAttribute(k_fc1, cudaFuncAttributeMaxDynamicSharedMemorySize, SMEMF);

    k_prep_w2b<<<(5 * 2 * 64 * 168 + 255) / 256, 256>>>(conv2_w);
    k_prep_fc1w<<<1024, 256>>>(fc1_w);
    k_conv1<<<1024, 392>>>(x, conv1_w, trelu_t);
    k_conv2<<<1568, 256, SMEM2>>>(conv2_b);
    k_fc1<<<dim3(16, 8), 256, SMEMF>>>(fc1_b);
    k_fc2<<<256, 256>>>(fc2_w, fc2_b, out);
}

// round 10
// speedup vs baseline: 2.5889x; 1.1452x over previous
#include <cuda_runtime.h>
#include <cuda_bf16.h>
#include <cstdint>

typedef unsigned long long ull;
typedef unsigned short u16;
typedef unsigned int u32;

// ---------------- device scratch (static, zero-initialized) ----------------
// conv1 out, packed-interleave layout: per (b, padded_y) row of 18 pixels,
// 36 k-groups of 16 elems; each group = 4 c-blocks of 8 u16:
// {hi[2c],hi[2c+1],lo[2c],lo[2c+1],hi[2c+8],hi[2c+9],lo[2c+8],lo[2c+9]}
__device__ __align__(16) u16   g_s1p[2048 * 18 * 18 * 2 * 32]; // halo stays 0
__device__ __align__(16) u16   g_s2h[2048 * 3136];          // conv2 out bf16 hi [b][q*64+co]
__device__ __align__(16) u16   g_s2l[2048 * 3136];          // conv2 out bf16 lo
__device__ __align__(16) float g_fc1[2048 * 1024];          // fc1 out (f32)
__device__ __align__(16) u16   g_fc1wh[1024 * 3136];        // fc1 w bf16 hi, K (q,co)
__device__ __align__(16) u16   g_fc1wl[1024 * 3136];        // fc1 w bf16 lo
__device__ __align__(16) u16   g_w2b[5 * 2 * 64 * 168];     // conv2 B [dy][plane][n][k pad 168]

// ---------------- f32x2 helpers ----------------
__device__ __forceinline__ ull ffma2(ull a, ull b, ull c) {
    ull d; asm("fma.rn.f32x2 %0, %1, %2, %3;" : "=l"(d) : "l"(a), "l"(b), "l"(c)); return d;
}
__device__ __forceinline__ ull dup2(float v) {
    ull d; asm("mov.b64 %0, {%1, %1};" : "=l"(d) : "f"(v)); return d;
}
__device__ __forceinline__ ull pk2(float lo, float hi) {
    ull d; asm("mov.b64 %0, {%1, %2};" : "=l"(d) : "f"(lo), "f"(hi)); return d;
}
__device__ __forceinline__ void upk2(ull v, float& lo, float& hi) {
    asm("mov.b64 {%0, %1}, %2;" : "=f"(lo), "=f"(hi) : "l"(v));
}

// ---------------- cp.async ----------------
__device__ __forceinline__ void cp16u(u32 saddr, const void* g) {
    asm volatile("cp.async.ca.shared.global [%0], [%1], 16;" :: "r"(saddr), "l"(g));
}
__device__ __forceinline__ void cp_commit() { asm volatile("cp.async.commit_group;"); }
__device__ __forceinline__ void cp_wait0()  { asm volatile("cp.async.wait_group 0;"); }
__device__ __forceinline__ void cp_wait1()  { asm volatile("cp.async.wait_group 1;"); }

// ---------------- mma.sync / ldmatrix ----------------
__device__ __forceinline__ void ldsm4(u32& r0, u32& r1, u32& r2, u32& r3, u32 addr) {
    asm volatile("ldmatrix.sync.aligned.m8n8.x4.shared.b16 {%0,%1,%2,%3}, [%4];"
                 : "=r"(r0), "=r"(r1), "=r"(r2), "=r"(r3) : "r"(addr));
}
__device__ __forceinline__ void mma16816(float* d, const u32* a, const u32* b) {
    asm volatile("mma.sync.aligned.m16n8k16.row.col.f32.bf16.bf16.f32 "
                 "{%0,%1,%2,%3}, {%4,%5,%6,%7}, {%8,%9}, {%0,%1,%2,%3};"
                 : "+f"(d[0]), "+f"(d[1]), "+f"(d[2]), "+f"(d[3])
                 : "r"(a[0]), "r"(a[1]), "r"(a[2]), "r"(a[3]), "r"(b[0]), "r"(b[1]));
}

__device__ __forceinline__ void ins4(float& a, float& b, float& c, float& d, float v) {
    if (v > d) {
        d = v;
        if (d > c) { float t = c; c = d; d = t;
            if (c > b) { t = b; b = c; c = t;
                if (b > a) { t = a; a = b; b = t; }
            }
        }
    }
}
__device__ __forceinline__ u32 bf16pack2(float x, float y) {
    __nv_bfloat16 hx = __float2bfloat16(x), hy = __float2bfloat16(y);
    return (u32)reinterpret_cast<u16&>(hx) | ((u32)reinterpret_cast<u16&>(hy) << 16);
}

// ============================================================================
// prep: conv2 B images [dy][plane][n=64][k pad 168], k = dx*32+ci, bf16 hi/lo
// ============================================================================
__global__ void k_prep_w2b(const float* __restrict__ w2) {
    int i = blockIdx.x * blockDim.x + threadIdx.x;
    if (i >= 5 * 2 * 64 * 168) return;
    int dy = i / 21504, r = i % 21504;
    int plane = r / 10752, r2 = r % 10752;
    int co = r2 / 168, k = r2 % 168;
    float v = 0.f;
    if (k < 160) {
        int dx = k >> 5, ci = k & 31;
        v = w2[(co * 32 + ci) * 25 + dy * 5 + dx];
    }
    __nv_bfloat16 h = __float2bfloat16(v);
    if (plane == 0) {
        g_w2b[i] = reinterpret_cast<u16&>(h);
    } else {
        __nv_bfloat16 l2 = __float2bfloat16(v - __bfloat162float(h));
        g_w2b[i] = reinterpret_cast<u16&>(l2);
    }
}

// ============================================================================
// prep: fc1 weight K-permute (k = co*49+q -> j = q*64+co) + bf16 hi/lo split
// ============================================================================
__global__ void __launch_bounds__(256) k_prep_fc1w(const float* __restrict__ w) {
    __shared__ float row[3136];
    int n = blockIdx.x;
    for (int i = threadIdx.x; i < 3136; i += 256) row[i] = w[n * 3136 + i];
    __syncthreads();
    for (int i = threadIdx.x; i < 3136; i += 256) {
        int q = i >> 6, co = i & 63;
        float v = row[co * 49 + q];
        __nv_bfloat16 h = __float2bfloat16(v);
        __nv_bfloat16 l2 = __float2bfloat16(v - __bfloat162float(h));
        g_fc1wh[n * 3136 + i] = reinterpret_cast<u16&>(h);
        g_fc1wl[n * 3136 + i] = reinterpret_cast<u16&>(l2);
    }
}

// ============================================================================
// conv1 v2 (1->32, 5x5, pad2) + top-4 mask + threshold ReLU + 2x2 maxpool.
// SINGLE conv pass: CTA = 784 threads = 1 image, thread = 1 pixel
// (quad-major: tid>>2 = pool quad, tid&3 = member). 16 f32x2 accumulators
// (lanes = channel pair). Pool via per-quad shfl. Output: packed-interleave
// hi/lo layout (g_s1p), halo stays zero. Bit-identical to the 2-pass version.
// ============================================================================
__global__ void __launch_bounds__(784) k_conv1(const float* __restrict__ xin,
                                               const float* __restrict__ w1,
                                               const float* __restrict__ tt) {
    __shared__ float s_img[1024];    // padded 32x32
    __shared__ ull   s_wp[400];      // [tap][chpair]: (w[2c][tap], w[2c+1][tap])
    __shared__ float s_t[32];

    const int tid = threadIdx.x;
    const int img = blockIdx.x;

    for (int i = tid; i < 1024; i += 784) s_img[i] = 0.f;
    for (int i = tid; i < 400; i += 784) {
        int tap = i >> 4, c16 = i & 15;
        s_wp[i] = pk2(w1[(2 * c16) * 25 + tap], w1[(2 * c16 + 1) * 25 + tap]);
    }
    if (tid < 32) s_t[tid] = tt[tid];
    __syncthreads();
    {   // interior load: 784 threads = 28x28 exactly
        int y = tid / 28, xx = tid % 28;
        s_img[(y + 2) * 32 + xx + 2] = xin[img * 784 + tid];
    }
    __syncthreads();

    // pixel decode (quad-major)
    const int q = tid >> 2, j = tid & 3;
    const int PY = q / 14, PX = q % 14;          // pool coords
    const int py = 2 * PY + (j >> 1), px = 2 * PX + (j & 1);
    const float* base = &s_img[py * 32 + px];

    // single conv pass: taps outer, 16 channel-pair accumulators
    ull acc[16];
#pragma unroll
    for (int c = 0; c < 16; c++) acc[c] = 0ull;
#pragma unroll
    for (int dy = 0; dy < 5; dy++)
#pragma unroll
        for (int dx = 0; dx < 5; dx++) {
            ull wd = dup2(base[dy * 32 + dx]);
            const ull* wp = &s_wp[(dy * 5 + dx) * 16];
#pragma unroll
            for (int c = 0; c < 16; c++) acc[c] = ffma2(wd, wp[c], acc[c]);
        }

    float vals[32];
#pragma unroll
    for (int c = 0; c < 16; c++) upk2(acc[c], vals[2 * c], vals[2 * c + 1]);

    // top-4 -> kth largest
    float a4 = -3.4e38f, b4 = -3.4e38f, c4 = -3.4e38f, d4 = -3.4e38f;
#pragma unroll
    for (int c = 0; c < 32; c++) ins4(a4, b4, c4, d4, vals[c]);

    // threshold-relu + quad max-pool (shfl within quad)
    const u32 lane = (u32)(tid & 31);
    const u32 qm = 0xFu << (lane & ~3u);
#pragma unroll
    for (int c = 0; c < 32; c++) {
        float v = vals[c];
        float r = (v >= d4) ? fmaxf(v - s_t[c], 0.f) : 0.f;
        r = fmaxf(r, __shfl_xor_sync(qm, r, 1));
        r = fmaxf(r, __shfl_xor_sync(qm, r, 2));
        vals[c] = r;
    }

    if (j == 0) {
        u16 oh[32], ol[32];
#pragma unroll
        for (int c = 0; c < 32; c++) {
            float v = vals[c];
            __nv_bfloat16 h = __float2bfloat16(v);
            oh[c] = reinterpret_cast<u16&>(h);
            __nv_bfloat16 l2 = __float2bfloat16(v - __bfloat162float(h));
            ol[c] = reinterpret_cast<u16&>(l2);
        }
        size_t gb = ((((size_t)img * 18 + (PY + 2)) * 18 + (PX + 2)) * 2) * 32;
#pragma unroll
        for (int g = 0; g < 2; g++) {
#pragma unroll
            for (int c = 0; c < 4; c++) {
                __align__(16) u16 buf[8];
                buf[0] = oh[g * 16 + 2 * c];     buf[1] = oh[g * 16 + 2 * c + 1];
                buf[2] = ol[g * 16 + 2 * c];     buf[3] = ol[g * 16 + 2 * c + 1];
                buf[4] = oh[g * 16 + 2 * c + 8]; buf[5] = oh[g * 16 + 2 * c + 9];
                buf[6] = ol[g * 16 + 2 * c + 8]; buf[7] = ol[g * 16 + 2 * c + 9];
                *reinterpret_cast<uint4*>(g_s1p + gb + g * 32 + c * 8) =
                    *reinterpret_cast<uint4*>(buf);
            }
        }
    }
}

// ============================================================================
// conv2 via mma.sync (bf16 hi/lo x3): 5 accumulated GEMMs, K=160 per dy.
// CTA = 256 threads / 8 warps, M=256 rows; warp = m32 x n64, 2 CTAs/SM.
// A fragments: one LDG.128 per (row, k-step) from packed-interleave layout.
// B smem double-buffered. Epilogue: shfl quad max-pool + bias + relu.
// ============================================================================
__global__ void __launch_bounds__(256, 2) k_conv2(const float* __restrict__ b2) {
    extern __shared__ __align__(16) char sm2[];
    u32 sB = (u32)__cvta_generic_to_shared(sm2);   // 2 x 43008 B buffers

    const int tid = threadIdx.x;
    const int warp = tid >> 5, lane = tid & 31;

    u32 grpb[4];
#pragma unroll
    for (int i = 0; i < 4; i++) {
        int r = warp * 32 + ((i & 1) << 3) + ((i >> 1) << 4) + (lane >> 2);
        int m = blockIdx.x * 256 + r;
        int g = m >> 2, j = m & 3;
        int b = g / 49, q = g % 49;
        int qy = q / 7, qx = q % 7;
        int py = 2 * qy + (j >> 1), px = 2 * qx + (j & 1);
        grpb[i] = (u32)(((b * 18 + py) * 18 + px) * 2) * 32u + (u32)(lane & 3) * 8u;
    }
    const u16* __restrict__ pp = g_s1p;

    for (int i = tid; i < 2688; i += 256)
        cp16u(sB + (u32)i * 16u, (const char*)g_w2b + (size_t)i * 16);
    cp_commit();

    float d[2][8][4];
#pragma unroll
    for (int mt = 0; mt < 2; mt++)
#pragma unroll
        for (int nt = 0; nt < 8; nt++)
#pragma unroll
            for (int e = 0; e < 4; e++) d[mt][nt][e] = 0.f;

    const u32 lrow = (u32)((lane & 7) + ((lane >> 4) << 3));
    const u32 lkb16 = (u32)(((lane >> 3) & 1) << 4);

    for (int dy = 0; dy < 5; dy++) {
        if (dy < 4) {
            u32 dst = sB + (u32)((dy + 1) & 1) * 43008u;
            const char* src = (const char*)g_w2b + (size_t)(dy + 1) * 43008u;
            for (int i = tid; i < 2688; i += 256)
                cp16u(dst + (u32)i * 16u, src + (size_t)i * 16);
            cp_commit();
            cp_wait1();
        } else {
            cp_wait0();
        }
        __syncthreads();

        const u32 dygrp = (u32)dy * 36u;
        const u32 bb = sB + (u32)(dy & 1) * 43008u;

#pragma unroll
        for (int s = 0; s < 10; s++) {
            const u32 goff = (dygrp + (u32)s) * 32u;
            u32 ah[2][4], al[2][4];
#pragma unroll
            for (int mt = 0; mt < 2; mt++) {
                uint4 q0 = *reinterpret_cast<const uint4*>(pp + grpb[mt * 2] + goff);
                uint4 q1 = *reinterpret_cast<const uint4*>(pp + grpb[mt * 2 + 1] + goff);
                ah[mt][0] = q0.x; al[mt][0] = q0.y; ah[mt][2] = q0.z; al[mt][2] = q0.w;
                ah[mt][1] = q1.x; al[mt][1] = q1.y; ah[mt][3] = q1.z; al[mt][3] = q1.w;
            }
            u32 bh[8][2], bl[8][2];
#pragma unroll
            for (int p = 0; p < 4; p++) {
                u32 ad = bb + ((u32)p * 16u + lrow) * 336u + (u32)s * 32u + lkb16;
                ldsm4(bh[2 * p][0], bh[2 * p][1], bh[2 * p + 1][0], bh[2 * p + 1][1], ad);
                ldsm4(bl[2 * p][0], bl[2 * p][1], bl[2 * p + 1][0], bl[2 * p + 1][1],
                      ad + 21504u);
            }
#pragma unroll
            for (int mt = 0; mt < 2; mt++)
#pragma unroll
                for (int nt = 0; nt < 8; nt++) mma16816(d[mt][nt], ah[mt], bh[nt]);
#pragma unroll
            for (int mt = 0; mt < 2; mt++)
#pragma unroll
                for (int nt = 0; nt < 8; nt++) mma16816(d[mt][nt], al[mt], bh[nt]);
#pragma unroll
            for (int mt = 0; mt < 2; mt++)
#pragma unroll
                for (int nt = 0; nt < 8; nt++) mma16816(d[mt][nt], ah[mt], bl[nt]);
        }
        __syncthreads();
    }

    // epilogue: quad max-pool + bias + relu -> bf16 hi/lo planes
    float bA[8], bB[8];
#pragma unroll
    for (int nt = 0; nt < 8; nt++) {
        int co = nt * 8 + 2 * (lane & 3);
        bA[nt] = b2[co]; bB[nt] = b2[co + 1];
    }
    bool act = ((lane & 12) == 0);
#pragma unroll
    for (int mt = 0; mt < 2; mt++)
#pragma unroll
        for (int rp = 0; rp < 2; rp++) {
            int G = blockIdx.x * 64 + warp * 8 + mt * 4 + rp * 2 + (lane >> 4);
            int b_ = G / 49, q_ = G % 49;
            size_t obase = (size_t)b_ * 3136 + q_ * 64;
#pragma unroll
            for (int nt = 0; nt < 8; nt++) {
                float v0 = d[mt][nt][2 * rp];
                float v1 = d[mt][nt][2 * rp + 1];
                v0 = fmaxf(v0, __shfl_xor_sync(0xffffffffu, v0, 4));
                v0 = fmaxf(v0, __shfl_xor_sync(0xffffffffu, v0, 8));
                v1 = fmaxf(v1, __shfl_xor_sync(0xffffffffu, v1, 4));
                v1 = fmaxf(v1, __shfl_xor_sync(0xffffffffu, v1, 8));
                if (act) {
                    float ox = fmaxf(v0 + bA[nt], 0.f);
                    float oy = fmaxf(v1 + bB[nt], 0.f);
                    __nv_bfloat16 hx = __float2bfloat16(ox), hy = __float2bfloat16(oy);
                    float lx = ox - __bfloat162float(hx);
                    float ly = oy - __bfloat162float(hy);
                    size_t idx = obase + nt * 8 + 2 * (lane & 3);
                    *reinterpret_cast<u32*>(g_s2h + idx) =
                        (u32)reinterpret_cast<u16&>(hx) | ((u32)reinterpret_cast<u16&>(hy) << 16);
                    *reinterpret_cast<u32*>(g_s2l + idx) = bf16pack2(lx, ly);
                }
            }
        }
}

// ============================================================================
// fc1 via mma.sync (bf16 hi/lo x3): M=2048, N=1024, K=3136.
// CTA 256 thr / 8 warps = M128 x N128; A and B both smem-staged (cp.async,
// 80B padded rows, conflict-free ldmatrix), double-buffered.
// ============================================================================
__global__ void __launch_bounds__(256) k_fc1(const float* __restrict__ b) {
    extern __shared__ __align__(16) char smf[];
    const u32 sbase = (u32)__cvta_generic_to_shared(smf);

    const int tid = threadIdx.x;
    const int warp = tid >> 5, lane = tid & 31;
    const int wm = warp >> 1, wn = warp & 1;
    const int bm = blockIdx.x * 128, bn = blockIdx.y * 128;

    const u32 lrow = (u32)((lane & 7) + ((lane >> 4) << 3));
    const u32 lkb16 = (u32)(((lane >> 3) & 1) << 4);
    const u32 arow16 = (u32)(lane & 15);
    const u32 acb16 = (u32)((lane >> 4) << 4);

    auto load_chunk = [&](int buf, int k0) {
        u32 abase = sbase + (u32)buf * 20480u;
        u32 bbase = sbase + 40960u + (u32)buf * 20480u;
        for (int i = tid; i < 2048; i += 256) {
            int sel = i >> 10;
            int r = i & 1023;
            int plane = r >> 9, rr = r & 511;
            int row = rr >> 2, qh = rr & 3;
            const u16* src;
            u32 dst;
            if (sel == 0) {
                src = (plane ? g_s2l : g_s2h) + (size_t)(bm + row) * 3136 + k0 + qh * 8;
                dst = abase;
            } else {
                src = (plane ? g_fc1wl : g_fc1wh) + (size_t)(bn + row) * 3136 + k0 + qh * 8;
                dst = bbase;
            }
            cp16u(dst + (u32)plane * 10240u + (u32)row * 80u + (u32)qh * 16u, src);
        }
    };

    load_chunk(0, 0);
    cp_commit();

    float d[2][8][4];
#pragma unroll
    for (int mt = 0; mt < 2; mt++)
#pragma unroll
        for (int nt = 0; nt < 8; nt++)
#pragma unroll
            for (int e = 0; e < 4; e++) d[mt][nt][e] = 0.f;

    for (int kt = 0; kt < 98; kt++) {
        if (kt < 97) {
            load_chunk((kt + 1) & 1, (kt + 1) * 32);
            cp_commit();
            cp_wait1();
        } else {
            cp_wait0();
        }
        __syncthreads();

        const u32 abuf = sbase + (u32)(kt & 1) * 20480u;
        const u32 bbuf = sbase + 40960u + (u32)(kt & 1) * 20480u;

#pragma unroll
        for (int ks = 0; ks < 2; ks++) {
            u32 ah[2][4], al[2][4];
#pragma unroll
            for (int mt = 0; mt < 2; mt++) {
                u32 ar = abuf + ((u32)(wm * 32 + mt * 16) + arow16) * 80u
                       + (u32)ks * 32u + acb16;
                ldsm4(ah[mt][0], ah[mt][1], ah[mt][2], ah[mt][3], ar);
                ldsm4(al[mt][0], al[mt][1], al[mt][2], al[mt][3], ar + 10240u);
            }
            u32 bh[8][2], bl[8][2];
#pragma unroll
            for (int p = 0; p < 4; p++) {
                u32 ad = bbuf + ((u32)(wn * 64 + p * 16) + lrow) * 80u
                       + (u32)ks * 32u + lkb16;
                ldsm4(bh[2 * p][0], bh[2 * p][1], bh[2 * p + 1][0], bh[2 * p + 1][1], ad);
                ldsm4(bl[2 * p][0], bl[2 * p][1], bl[2 * p + 1][0], bl[2 * p + 1][1],
                      ad + 10240u);
            }
#pragma unroll
            for (int mt = 0; mt < 2; mt++)
#pragma unroll
                for (int nt = 0; nt < 8; nt++) mma16816(d[mt][nt], ah[mt], bh[nt]);
#pragma unroll
            for (int mt = 0; mt < 2; mt++)
#pragma unroll
                for (int nt = 0; nt < 8; nt++) mma16816(d[mt][nt], al[mt], bh[nt]);
#pragma unroll
            for (int mt = 0; mt < 2; mt++)
#pragma unroll
                for (int nt = 0; nt < 8; nt++) mma16816(d[mt][nt], ah[mt], bl[nt]);
        }
        __syncthreads();
    }

#pragma unroll
    for (int nt = 0; nt < 8; nt++) {
        int col = bn + wn * 64 + nt * 8 + (lane & 3) * 2;
        float b0 = b[col], b1 = b[col + 1];
#pragma unroll
        for (int mt = 0; mt < 2; mt++)
#pragma unroll
            for (int rp = 0; rp < 2; rp++) {
                int row = bm + wm * 32 + mt * 16 + (lane >> 2) + rp * 8;
                float2 o;
                o.x = fmaxf(d[mt][nt][2 * rp] + b0, 0.f);
                o.y = fmaxf(d[mt][nt][2 * rp + 1] + b1, 0.f);
                *reinterpret_cast<float2*>(&g_fc1[(size_t)row * 1024 + col]) = o;
            }
    }
}

// ============================================================================
// fc2: [2048,1024] x [10,1024]^T + b. Warp per row.
// ============================================================================
__global__ void __launch_bounds__(256) k_fc2(const float* __restrict__ w,
                                             const float* __restrict__ b,
                                             float* __restrict__ out) {
    int warp = threadIdx.x >> 5, lane = threadIdx.x & 31;
    int row = blockIdx.x * 8 + warp;
    const float* a = &g_fc1[row * 1024];
    float acc[10];
#pragma unroll
    for (int n = 0; n < 10; n++) acc[n] = 0.f;
    for (int k = lane; k < 1024; k += 32) {
        float av = a[k];
#pragma unroll
        for (int n = 0; n < 10; n++) acc[n] += av * w[n * 1024 + k];
    }
#pragma unroll
    for (int n = 0; n < 10; n++)
#pragma unroll
        for (int off = 16; off > 0; off >>= 1)
            acc[n] += __shfl_xor_sync(0xffffffffu, acc[n], off);
    if (lane == 0) {
#pragma unroll
        for (int n = 0; n < 10; n++) out[row * 10 + n] = acc[n] + b[n];
    }
}

// ============================================================================
extern "C" void kernel_launch(void* const* d_in, const int* in_sizes, int n_in,
                              void* d_out, int out_size) {
    const float* x       = (const float*)d_in[0];
    const float* conv1_w = (const float*)d_in[1];
    const float* trelu_t = (const float*)d_in[2];
    const float* conv2_w = (const float*)d_in[3];
    const float* conv2_b = (const float*)d_in[4];
    const float* fc1_w   = (const float*)d_in[5];
    const float* fc1_b   = (const float*)d_in[6];
    const float* fc2_w   = (const float*)d_in[7];
    const float* fc2_b   = (const float*)d_in[8];
    float* out = (float*)d_out;

    const int SMEM2 = 2 * 43008;
    const int SMEMF = 2 * 40960;
    cudaFuncSetAttribute(k_conv2, cudaFuncAttributeMaxDynamicSharedMemorySize, SMEM2);
    cudaFuncSetAttribute(k_fc1, cudaFuncAttributeMaxDynamicSharedMemorySize, SMEMF);

    k_prep_w2b<<<(5 * 2 * 64 * 168 + 255) / 256, 256>>>(conv2_w);
    k_prep_fc1w<<<1024, 256>>>(fc1_w);
    k_conv1<<<2048, 784>>>(x, conv1_w, trelu_t);
    k_conv2<<<1568, 256, SMEM2>>>(conv2_b);
    k_fc1<<<dim3(16, 8), 256, SMEMF>>>(fc1_b);
    k_fc2<<<256, 256>>>(fc2_w, fc2_b, out);
}